// round 1
// baseline (speedup 1.0000x reference)
#include <cuda_runtime.h>
#include <cstdint>
#include <math.h>

#define BATCH 2048
#define NMOL 16
#define HEADS 8
#define CA 512
#define NROWS (BATCH * NMOL)   // 32768
#define K1PAD 80               // 70 padded to 80 (mult of 16)
#define K2 512

// fp32 scratch for K, Q, V: 3 x 32768 x 512 floats (192 MB)
__device__ float g_scratch[3ULL * NROWS * CA];

// ---------------------------------------------------------------------------
// tf32 helpers
// ---------------------------------------------------------------------------
__device__ __forceinline__ unsigned f2tf(float x) {
    unsigned r;
    asm("cvt.rna.tf32.f32 %0, %1;" : "=r"(r) : "f"(x));
    return r;
}

__device__ __forceinline__ void mma_tf32(float d[4], const unsigned a[4], const unsigned b[2]) {
    asm volatile(
        "mma.sync.aligned.m16n8k8.row.col.f32.tf32.tf32.f32 "
        "{%0,%1,%2,%3}, {%4,%5,%6,%7}, {%8,%9}, {%0,%1,%2,%3};\n"
        : "+f"(d[0]), "+f"(d[1]), "+f"(d[2]), "+f"(d[3])
        : "r"(a[0]), "r"(a[1]), "r"(a[2]), "r"(a[3]),
          "r"(b[0]), "r"(b[1]));
}

// ---------------------------------------------------------------------------
// Fused MLP kernel: out = silu(XE @ Wh + bh) @ Wo + bo  for 64 rows per CTA.
// blockIdx.y in {0,1,2} selects the k/q/v weight set.
// smem (floats): XE[64][84] | Bsm[16][520] | H[64][516]
// ---------------------------------------------------------------------------
#define XE_S 84
#define B_S 520
#define H_S 516
#define XE_OFF 0
#define B_OFF (64 * XE_S)            // 5376
#define H_OFF (B_OFF + 16 * B_S)     // 13696
#define SMEM_FLOATS (H_OFF + 64 * H_S)  // 46720 floats = 186880 B

__global__ void __launch_bounds__(512, 1)
mlp_kernel(const float* __restrict__ x, const float* __restrict__ pos,
           const float* __restrict__ Wkh, const float* __restrict__ bkh,
           const float* __restrict__ Wko, const float* __restrict__ bko,
           const float* __restrict__ Wqh, const float* __restrict__ bqh,
           const float* __restrict__ Wqo, const float* __restrict__ bqo,
           const float* __restrict__ Wvh, const float* __restrict__ bvh,
           const float* __restrict__ Wvo, const float* __restrict__ bvo)
{
    extern __shared__ float sm[];
    float* XE  = sm + XE_OFF;
    float* Bsm = sm + B_OFF;
    float* H   = sm + H_OFF;

    const int tid = threadIdx.x;
    const int by  = blockIdx.y;
    const float* Wh = (by == 0) ? Wkh : (by == 1 ? Wqh : Wvh);
    const float* bh = (by == 0) ? bkh : (by == 1 ? bqh : bvh);
    const float* Wo = (by == 0) ? Wko : (by == 1 ? Wqo : Wvo);
    const float* bo = (by == 0) ? bko : (by == 1 ? bqo : bvo);
    float* outg = g_scratch + (size_t)by * NROWS * CA;

    const int row0 = blockIdx.x * 64;

    // ---- build XE tile: [x | pos_emb | zero-pad] -> 64 x 80 (stride 84) ----
    for (int idx = tid; idx < 64 * XE_S; idx += 512) {
        int r = idx / XE_S, c = idx - r * XE_S;
        int rg = row0 + r;
        int m  = rg & 15;
        float v = 0.f;
        if (c < 64)      v = x[(size_t)rg * 64 + c];
        else if (c < 70) v = pos[m * 6 + (c - 64)];
        XE[r * XE_S + c] = v;
    }

    const int lane = tid & 31;
    const int warp = tid >> 5;            // 16 warps; each owns 32 N-cols
    const int g  = lane >> 2;             // groupID
    const int t4 = lane & 3;              // threadID in group
    const int nw = warp * 32;

    float  acc[4][4][4];
    float4 pf[4];

    auto loadPF = [&](int kc, int Krows, const float* W) {
        #pragma unroll
        for (int i = 0; i < 4; i++) {
            int f4 = tid + i * 512;
            int kk = f4 >> 7;
            int n  = (f4 & 127) << 2;
            int r  = kc * 16 + kk;
            if (r < Krows) pf[i] = *(const float4*)(W + (size_t)r * 512 + n);
            else           pf[i] = make_float4(0.f, 0.f, 0.f, 0.f);
        }
    };
    auto storePF = [&]() {
        #pragma unroll
        for (int i = 0; i < 4; i++) {
            int f4 = tid + i * 512;
            int kk = f4 >> 7;
            int n  = (f4 & 127) << 2;
            *(float4*)(Bsm + kk * B_S + n) = pf[i];
        }
    };

    auto gemm = [&](const float* A, int As, int nchunks, int Krows, const float* W) {
        loadPF(0, Krows, W);
        for (int kc = 0; kc < nchunks; ++kc) {
            __syncthreads();
            storePF();
            __syncthreads();
            if (kc + 1 < nchunks) loadPF(kc + 1, Krows, W);
            #pragma unroll
            for (int ks = 0; ks < 2; ++ks) {
                const int k0 = kc * 16 + ks * 8;  // col in A
                const int kl = ks * 8;            // row in Bsm
                unsigned af[4][4], bf[4][2];
                #pragma unroll
                for (int mt = 0; mt < 4; mt++) {
                    const float* Ar = A + (mt * 16 + g) * As + k0 + t4;
                    af[mt][0] = f2tf(Ar[0]);
                    af[mt][1] = f2tf(Ar[8 * As]);
                    af[mt][2] = f2tf(Ar[4]);
                    af[mt][3] = f2tf(Ar[8 * As + 4]);
                }
                #pragma unroll
                for (int nt = 0; nt < 4; nt++) {
                    const float* Br = Bsm + (kl + t4) * B_S + nw + nt * 8 + g;
                    bf[nt][0] = f2tf(Br[0]);
                    bf[nt][1] = f2tf(Br[4 * B_S]);
                }
                #pragma unroll
                for (int mt = 0; mt < 4; mt++)
                    #pragma unroll
                    for (int nt = 0; nt < 4; nt++)
                        mma_tf32(acc[mt][nt], af[mt], bf[nt]);
            }
        }
    };

    // ---------------- GEMM1: H = silu(XE @ Wh + bh) ----------------
    #pragma unroll
    for (int i = 0; i < 4; i++)
        #pragma unroll
        for (int j = 0; j < 4; j++)
            #pragma unroll
            for (int q = 0; q < 4; q++) acc[i][j][q] = 0.f;

    gemm(XE, XE_S, K1PAD / 16, 70, Wh);

    #pragma unroll
    for (int mt = 0; mt < 4; mt++) {
        #pragma unroll
        for (int nt = 0; nt < 4; nt++) {
            int col = nw + nt * 8 + 2 * t4;
            int r0  = mt * 16 + g;
            float b0 = bh[col], b1 = bh[col + 1];
            float h;
            h = acc[mt][nt][0] + b0; h = h / (1.f + __expf(-h)); H[r0 * H_S + col]           = h;
            h = acc[mt][nt][1] + b1; h = h / (1.f + __expf(-h)); H[r0 * H_S + col + 1]       = h;
            h = acc[mt][nt][2] + b0; h = h / (1.f + __expf(-h)); H[(r0 + 8) * H_S + col]     = h;
            h = acc[mt][nt][3] + b1; h = h / (1.f + __expf(-h)); H[(r0 + 8) * H_S + col + 1] = h;
        }
    }

    // ---------------- GEMM2: out = H @ Wo + bo ----------------
    #pragma unroll
    for (int i = 0; i < 4; i++)
        #pragma unroll
        for (int j = 0; j < 4; j++)
            #pragma unroll
            for (int q = 0; q < 4; q++) acc[i][j][q] = 0.f;

    gemm(H, H_S, K2 / 16, 512, Wo);

    #pragma unroll
    for (int mt = 0; mt < 4; mt++) {
        #pragma unroll
        for (int nt = 0; nt < 4; nt++) {
            int col = nw + nt * 8 + 2 * t4;
            int r0  = mt * 16 + g;
            float b0 = bo[col], b1 = bo[col + 1];
            size_t base0 = (size_t)(row0 + r0) * 512 + col;
            size_t base1 = (size_t)(row0 + r0 + 8) * 512 + col;
            outg[base0]     = acc[mt][nt][0] + b0;
            outg[base0 + 1] = acc[mt][nt][1] + b1;
            outg[base1]     = acc[mt][nt][2] + b0;
            outg[base1 + 1] = acc[mt][nt][3] + b1;
        }
    }
}

// ---------------------------------------------------------------------------
// Attention kernel: one CTA per batch element.
// arg[i,j,c] = fm_i fm_j (k_i,c . q_j,c)/8 ; w = softplus+1e-5, zero diag,
// normalize over j; out[i,d] = sum_{j,c} fm_j w v[j,c,d]
// smem: sk[16][516] | sq[16][516] | ws[2048]
// ---------------------------------------------------------------------------
#define SK_S 516
#define ATTN_SMEM_FLOATS (2 * 16 * SK_S + 2048)   // 18560 floats = 74240 B

__global__ void __launch_bounds__(256)
attn_kernel(const float* __restrict__ fm, float* __restrict__ out)
{
    extern __shared__ float sm[];
    float* sk = sm;
    float* sq = sm + 16 * SK_S;
    float* ws = sq + 16 * SK_S;

    const int b   = blockIdx.x;
    const int tid = threadIdx.x;
    const float* K = g_scratch + (size_t)b * NMOL * CA;
    const float* Q = g_scratch + (size_t)NROWS * CA + (size_t)b * NMOL * CA;
    const float* V = g_scratch + 2ULL * NROWS * CA + (size_t)b * NMOL * CA;

    for (int idx = tid; idx < NMOL * CA; idx += 256) {
        int i = idx >> 9, c = idx & 511;
        sk[i * SK_S + c] = K[idx];
        sq[i * SK_S + c] = Q[idx];
    }
    __syncthreads();

    // scores: thread owns (i-pair, head c, 4 j's): 8 x 8 x 4 = 256 units
    {
        int i2 = tid >> 5;            // 0..7 -> rows 2*i2, 2*i2+1
        int c  = (tid >> 2) & 7;
        int jb = (tid & 3) * 4;
        float a2[2][4];
        #pragma unroll
        for (int ii = 0; ii < 2; ii++)
            #pragma unroll
            for (int jj = 0; jj < 4; jj++) a2[ii][jj] = 0.f;

        const float* k0 = sk + (2 * i2) * SK_S + c * 64;
        const float* k1 = k0 + SK_S;
        #pragma unroll
        for (int a4 = 0; a4 < 16; a4++) {
            float4 kv0 = *(const float4*)(k0 + a4 * 4);
            float4 kv1 = *(const float4*)(k1 + a4 * 4);
            #pragma unroll
            for (int jj = 0; jj < 4; jj++) {
                float4 qv = *(const float4*)(sq + (jb + jj) * SK_S + c * 64 + a4 * 4);
                a2[0][jj] += kv0.x * qv.x + kv0.y * qv.y + kv0.z * qv.z + kv0.w * qv.w;
                a2[1][jj] += kv1.x * qv.x + kv1.y * qv.y + kv1.z * qv.z + kv1.w * qv.w;
            }
        }
        #pragma unroll
        for (int ii = 0; ii < 2; ii++) {
            int i = 2 * i2 + ii;
            float fmi = fm[i];
            #pragma unroll
            for (int jj = 0; jj < 4; jj++) {
                int j = jb + jj;
                float arg = a2[ii][jj] * 0.125f * fmi * fm[j];
                float w;
                if (i == j) w = 0.f;
                else {
                    float sp = (arg > 20.f) ? arg : log1pf(__expf(arg));
                    w = sp + 1e-5f;
                }
                ws[(i * 8 + c) * 16 + j] = w;
            }
        }
    }
    __syncthreads();

    // normalize over j, fold fm[j]
    if (tid < 128) {
        float* row = ws + tid * 16;
        float s = 0.f;
        #pragma unroll
        for (int j = 0; j < 16; j++) s += row[j];
        float inv = 1.f / s;
        #pragma unroll
        for (int j = 0; j < 16; j++) row[j] = row[j] * inv * fm[j];
    }
    __syncthreads();

    // load V into sk (reuse)
    for (int idx = tid; idx < NMOL * CA; idx += 256) {
        int i = idx >> 9, c = idx & 511;
        sk[i * SK_S + c] = V[idx];
    }
    __syncthreads();

    // combine: thread owns (d, 4 i's = {ib, ib+4, ib+8, ib+12})
    {
        int d  = tid & 63;
        int ib = tid >> 6;   // 0..3
        float a4[4] = {0.f, 0.f, 0.f, 0.f};
        #pragma unroll
        for (int c = 0; c < 8; c++) {
            #pragma unroll
            for (int j = 0; j < 16; j++) {
                float vv = sk[j * SK_S + c * 64 + d];
                #pragma unroll
                for (int ii = 0; ii < 4; ii++) {
                    int i = ii * 4 + ib;
                    a4[ii] += ws[(i * 8 + c) * 16 + j] * vv;
                }
            }
        }
        #pragma unroll
        for (int ii = 0; ii < 4; ii++) {
            int i = ii * 4 + ib;
            out[(size_t)b * 1024 + i * 64 + d] = a4[ii];
        }
    }
}

// ---------------------------------------------------------------------------
extern "C" void kernel_launch(void* const* d_in, const int* in_sizes, int n_in,
                              void* d_out, int out_size) {
    const float* x   = (const float*)d_in[0];
    const float* fm  = (const float*)d_in[1];
    const float* Wkh = (const float*)d_in[2];
    const float* bkh = (const float*)d_in[3];
    const float* Wko = (const float*)d_in[4];
    const float* bko = (const float*)d_in[5];
    const float* Wqh = (const float*)d_in[6];
    const float* bqh = (const float*)d_in[7];
    const float* Wqo = (const float*)d_in[8];
    const float* bqo = (const float*)d_in[9];
    const float* Wvh = (const float*)d_in[10];
    const float* bvh = (const float*)d_in[11];
    const float* Wvo = (const float*)d_in[12];
    const float* bvo = (const float*)d_in[13];
    const float* pos = (const float*)d_in[14];
    float* out = (float*)d_out;

    cudaFuncSetAttribute(mlp_kernel, cudaFuncAttributeMaxDynamicSharedMemorySize,
                         SMEM_FLOATS * 4);
    cudaFuncSetAttribute(attn_kernel, cudaFuncAttributeMaxDynamicSharedMemorySize,
                         ATTN_SMEM_FLOATS * 4);

    dim3 grid(NROWS / 64, 3);
    mlp_kernel<<<grid, 512, SMEM_FLOATS * 4>>>(x, pos,
        Wkh, bkh, Wko, bko, Wqh, bqh, Wqo, bqo, Wvh, bvh, Wvo, bvo);
    attn_kernel<<<BATCH, 256, ATTN_SMEM_FLOATS * 4>>>(fm, out);
}

// round 2
// speedup vs baseline: 1.0911x; 1.0911x over previous
#include <cuda_runtime.h>
#include <cstdint>
#include <math.h>

#define BATCH 2048
#define NMOL 16
#define CA 512
#define NROWS (BATCH * NMOL)   // 32768
#define K1PAD 80               // 70 padded to 80
#define K2 512

// fp32 scratch for K, Q, V: 3 x 32768 x 512 floats (192 MB)
__device__ float g_scratch[3ULL * NROWS * CA];

// ---------------------------------------------------------------------------
__device__ __forceinline__ unsigned f2tf(float x) {
    unsigned r;
    asm("cvt.rna.tf32.f32 %0, %1;" : "=r"(r) : "f"(x));
    return r;
}

__device__ __forceinline__ void mma_tf32(float d[4], const unsigned a[4], const unsigned b[2]) {
    asm volatile(
        "mma.sync.aligned.m16n8k8.row.col.f32.tf32.tf32.f32 "
        "{%0,%1,%2,%3}, {%4,%5,%6,%7}, {%8,%9}, {%0,%1,%2,%3};\n"
        : "+f"(d[0]), "+f"(d[1]), "+f"(d[2]), "+f"(d[3])
        : "r"(a[0]), "r"(a[1]), "r"(a[2]), "r"(a[3]),
          "r"(b[0]), "r"(b[1]));
}

// pair transform: element k -> position pairing (k, k+4) adjacently within 8-blocks
__device__ __forceinline__ int tp(int k) {
    return (k & ~7) + ((k & 3) << 1) + ((k >> 2) & 1);
}

// ---------------------------------------------------------------------------
// Fused MLP: out = silu(XE @ Wh + bh) @ Wo + bo, 64 rows/CTA, tf32 mma.
// All smem operands stored as pre-converted tf32 bit patterns in
// fragment-paired layouts; strides ≡ 8 (mod 32) words -> conflict-free LDS.64.
// smem: HA[64*520] (XE aliases its head, stride 104) | B2[2][8*1032]
// ---------------------------------------------------------------------------
#define XA_S 104
#define HA_S 520
#define SB   1032
#define B2_OFF (64 * HA_S)                     // 33280 words
#define SMEM_FLOATS (B2_OFF + 2 * 8 * SB)      // 49792 words = 199168 B

__global__ void __launch_bounds__(512, 1)
mlp_kernel(const float* __restrict__ x, const float* __restrict__ pos,
           const float* __restrict__ Wkh, const float* __restrict__ bkh,
           const float* __restrict__ Wko, const float* __restrict__ bko,
           const float* __restrict__ Wqh, const float* __restrict__ bqh,
           const float* __restrict__ Wqo, const float* __restrict__ bqo,
           const float* __restrict__ Wvh, const float* __restrict__ bvh,
           const float* __restrict__ Wvo, const float* __restrict__ bvo)
{
    extern __shared__ unsigned smu[];
    unsigned* HAu = smu;            // paired tf32 H (and XE alias)
    unsigned* B2u = smu + B2_OFF;   // double-buffered paired tf32 W tiles

    const int tid = threadIdx.x;
    const int by  = blockIdx.y;
    const float* Wh = (by == 0) ? Wkh : (by == 1 ? Wqh : Wvh);
    const float* bh = (by == 0) ? bkh : (by == 1 ? bqh : bvh);
    const float* Wo = (by == 0) ? Wko : (by == 1 ? Wqo : Wvo);
    const float* bo = (by == 0) ? bko : (by == 1 ? bqo : bvo);
    float* outg = g_scratch + (size_t)by * NROWS * CA;

    const int row0 = blockIdx.x * 64;

    // ---- XE tile (tf32, paired layout, stride XA_S) ----
    for (int idx = tid; idx < 64 * 80; idx += 512) {
        int r = idx / 80, c = idx - r * 80;
        int rg = row0 + r;
        float v = 0.f;
        if (c < 64)      v = x[(size_t)rg * 64 + c];
        else if (c < 70) v = pos[(rg & 15) * 6 + (c - 64)];
        HAu[r * XA_S + tp(c)] = f2tf(v);
    }

    const int lane = tid & 31;
    const int warp = tid >> 5;
    const int g  = lane >> 2;
    const int t4 = lane & 3;
    const int nw = warp * 32;

    float  acc[4][4][4];
    float4 pf[4];

    // staging geometry (per thread, 2 quad-pairs)
    int pp[2], nn4[2];
    #pragma unroll
    for (int i = 0; i < 2; i++) {
        int f = tid + i * 512;
        pp[i]  = f >> 7;                 // 0..7 pair-row
        nn4[i] = (f & 127) << 2;         // n base (4 cols)
    }

    auto loadPF = [&](int kc, int Krows, const float* W) {
        #pragma unroll
        for (int i = 0; i < 2; i++) {
            int klo = kc * 16 + (pp[i] & 3) + ((pp[i] & 4) << 1);
            int khi = klo + 4;
            pf[2*i]   = (klo < Krows) ? *(const float4*)(W + (size_t)klo * 512 + nn4[i])
                                      : make_float4(0.f,0.f,0.f,0.f);
            pf[2*i+1] = (khi < Krows) ? *(const float4*)(W + (size_t)khi * 512 + nn4[i])
                                      : make_float4(0.f,0.f,0.f,0.f);
        }
    };
    auto storePF = [&](int buf) {
        unsigned* base = B2u + buf * (8 * SB);
        #pragma unroll
        for (int i = 0; i < 2; i++) {
            unsigned* dst = base + pp[i] * SB + (nn4[i] << 1);
            uint4 s0, s1;
            s0.x = f2tf(pf[2*i].x); s0.y = f2tf(pf[2*i+1].x);
            s0.z = f2tf(pf[2*i].y); s0.w = f2tf(pf[2*i+1].y);
            s1.x = f2tf(pf[2*i].z); s1.y = f2tf(pf[2*i+1].z);
            s1.z = f2tf(pf[2*i].w); s1.w = f2tf(pf[2*i+1].w);
            *(uint4*)(dst)     = s0;
            *(uint4*)(dst + 4) = s1;
        }
    };

    auto gemm = [&](const unsigned* Au, int As, int nchunks, int Krows, const float* W) {
        loadPF(0, Krows, W);
        for (int kc = 0; kc < nchunks; ++kc) {
            storePF(kc & 1);
            __syncthreads();
            if (kc + 1 < nchunks) loadPF(kc + 1, Krows, W);
            const unsigned* Br = B2u + (kc & 1) * (8 * SB);
            #pragma unroll
            for (int ks = 0; ks < 2; ++ks) {
                unsigned af[4][4], bf[4][2];
                #pragma unroll
                for (int mt = 0; mt < 4; mt++) {
                    const unsigned* pa = Au + (mt*16 + g) * As + (kc*2 + ks)*8 + (t4 << 1);
                    uint2 lo = *(const uint2*)pa;
                    uint2 hi = *(const uint2*)(pa + 8 * As);
                    af[mt][0] = lo.x; af[mt][1] = hi.x;
                    af[mt][2] = lo.y; af[mt][3] = hi.y;
                }
                #pragma unroll
                for (int nt = 0; nt < 4; nt++) {
                    uint2 b = *(const uint2*)(Br + (t4 + 4*ks) * SB + ((nw + nt*8 + g) << 1));
                    bf[nt][0] = b.x; bf[nt][1] = b.y;
                }
                #pragma unroll
                for (int mt = 0; mt < 4; mt++)
                    #pragma unroll
                    for (int nt = 0; nt < 4; nt++)
                        mma_tf32(acc[mt][nt], af[mt], bf[nt]);
            }
        }
    };

    // ---------------- GEMM1: H = silu(XE @ Wh + bh) ----------------
    #pragma unroll
    for (int i = 0; i < 4; i++)
        #pragma unroll
        for (int j = 0; j < 4; j++)
            #pragma unroll
            for (int q = 0; q < 4; q++) acc[i][j][q] = 0.f;

    gemm(HAu, XA_S, K1PAD / 16, 70, Wh);

    __syncthreads();   // all XE reads done before overwriting region with H

    #pragma unroll
    for (int mt = 0; mt < 4; mt++) {
        #pragma unroll
        for (int nt = 0; nt < 4; nt++) {
            int col = nw + nt * 8 + 2 * t4;
            int r0  = mt * 16 + g;
            float b0 = bh[col], b1 = bh[col + 1];
            float h;
            h = acc[mt][nt][0] + b0; h = h / (1.f + __expf(-h)); HAu[r0 * HA_S + tp(col)]         = f2tf(h);
            h = acc[mt][nt][1] + b1; h = h / (1.f + __expf(-h)); HAu[r0 * HA_S + tp(col + 1)]     = f2tf(h);
            h = acc[mt][nt][2] + b0; h = h / (1.f + __expf(-h)); HAu[(r0+8) * HA_S + tp(col)]     = f2tf(h);
            h = acc[mt][nt][3] + b1; h = h / (1.f + __expf(-h)); HAu[(r0+8) * HA_S + tp(col + 1)] = f2tf(h);
        }
    }
    __syncthreads();

    // ---------------- GEMM2: out = H @ Wo + bo ----------------
    #pragma unroll
    for (int i = 0; i < 4; i++)
        #pragma unroll
        for (int j = 0; j < 4; j++)
            #pragma unroll
            for (int q = 0; q < 4; q++) acc[i][j][q] = 0.f;

    gemm(HAu, HA_S, K2 / 16, 512, Wo);

    #pragma unroll
    for (int mt = 0; mt < 4; mt++) {
        #pragma unroll
        for (int nt = 0; nt < 4; nt++) {
            int col = nw + nt * 8 + 2 * t4;
            int r0  = mt * 16 + g;
            float b0 = bo[col], b1 = bo[col + 1];
            size_t base0 = (size_t)(row0 + r0) * 512 + col;
            size_t base1 = (size_t)(row0 + r0 + 8) * 512 + col;
            outg[base0]     = acc[mt][nt][0] + b0;
            outg[base0 + 1] = acc[mt][nt][1] + b1;
            outg[base1]     = acc[mt][nt][2] + b0;
            outg[base1 + 1] = acc[mt][nt][3] + b1;
        }
    }
}

// ---------------------------------------------------------------------------
// Attention kernel: one CTA per batch element. V prefetched into registers at
// kernel start (hides second DRAM round-trip behind score compute).
// smem: sk[16][516] | sq[16][516] | ws[2048]  (74 KB -> 3 CTAs/SM)
// ---------------------------------------------------------------------------
#define SK_S 516
#define ATTN_SMEM_FLOATS (2 * 16 * SK_S + 2048)

__global__ void __launch_bounds__(256)
attn_kernel(const float* __restrict__ fm, float* __restrict__ out)
{
    extern __shared__ float sm[];
    float* sk = sm;
    float* sq = sm + 16 * SK_S;
    float* ws = sq + 16 * SK_S;

    const int b   = blockIdx.x;
    const int tid = threadIdx.x;
    const float* K = g_scratch + (size_t)b * NMOL * CA;
    const float* Q = g_scratch + (size_t)NROWS * CA + (size_t)b * NMOL * CA;
    const float* V = g_scratch + 2ULL * NROWS * CA + (size_t)b * NMOL * CA;

    // prefetch V into registers (8 x LDG.128)
    float4 v4[8];
    #pragma unroll
    for (int k = 0; k < 8; k++)
        v4[k] = ((const float4*)V)[tid + k * 256];

    // stage K, Q into smem (float4 both directions)
    #pragma unroll
    for (int k = 0; k < 8; k++) {
        int f = tid + k * 256;
        int i = f >> 7, c = (f & 127) << 2;
        *(float4*)(sk + i * SK_S + c) = ((const float4*)K)[f];
        *(float4*)(sq + i * SK_S + c) = ((const float4*)Q)[f];
    }
    __syncthreads();

    // scores: thread owns (i-pair, head c, 4 j's)
    {
        int i2 = tid >> 5;
        int c  = (tid >> 2) & 7;
        int jb = (tid & 3) * 4;
        float a2[2][4];
        #pragma unroll
        for (int ii = 0; ii < 2; ii++)
            #pragma unroll
            for (int jj = 0; jj < 4; jj++) a2[ii][jj] = 0.f;

        const float* k0 = sk + (2 * i2) * SK_S + c * 64;
        const float* k1 = k0 + SK_S;
        #pragma unroll
        for (int a4 = 0; a4 < 16; a4++) {
            float4 kv0 = *(const float4*)(k0 + a4 * 4);
            float4 kv1 = *(const float4*)(k1 + a4 * 4);
            #pragma unroll
            for (int jj = 0; jj < 4; jj++) {
                float4 qv = *(const float4*)(sq + (jb + jj) * SK_S + c * 64 + a4 * 4);
                a2[0][jj] += kv0.x * qv.x + kv0.y * qv.y + kv0.z * qv.z + kv0.w * qv.w;
                a2[1][jj] += kv1.x * qv.x + kv1.y * qv.y + kv1.z * qv.z + kv1.w * qv.w;
            }
        }
        #pragma unroll
        for (int ii = 0; ii < 2; ii++) {
            int i = 2 * i2 + ii;
            float fmi = fm[i];
            #pragma unroll
            for (int jj = 0; jj < 4; jj++) {
                int j = jb + jj;
                float arg = a2[ii][jj] * 0.125f * fmi * fm[j];
                float w;
                if (i == j) w = 0.f;
                else {
                    float sp = (arg > 20.f) ? arg : log1pf(__expf(arg));
                    w = sp + 1e-5f;
                }
                ws[(i * 8 + c) * 16 + j] = w;
            }
        }
    }
    __syncthreads();

    // normalize over j (threads 0..127) ; concurrently store V regs -> sk
    if (tid < 128) {
        float* row = ws + tid * 16;
        float s = 0.f;
        #pragma unroll
        for (int j = 0; j < 16; j++) s += row[j];
        float inv = 1.f / s;
        #pragma unroll
        for (int j = 0; j < 16; j++) row[j] = row[j] * inv * fm[j];
    }
    #pragma unroll
    for (int k = 0; k < 8; k++) {
        int f = tid + k * 256;
        int i = f >> 7, c = (f & 127) << 2;
        *(float4*)(sk + i * SK_S + c) = v4[k];
    }
    __syncthreads();

    // combine: thread owns (d, 4 i's)
    {
        int d  = tid & 63;
        int ib = tid >> 6;
        float a4[4] = {0.f, 0.f, 0.f, 0.f};
        #pragma unroll
        for (int c = 0; c < 8; c++) {
            #pragma unroll
            for (int j = 0; j < 16; j++) {
                float vv = sk[j * SK_S + c * 64 + d];
                #pragma unroll
                for (int ii = 0; ii < 4; ii++) {
                    int i = ii * 4 + ib;
                    a4[ii] += ws[(i * 8 + c) * 16 + j] * vv;
                }
            }
        }
        #pragma unroll
        for (int ii = 0; ii < 4; ii++) {
            int i = ii * 4 + ib;
            out[(size_t)b * 1024 + i * 64 + d] = a4[ii];
        }
    }
}

// ---------------------------------------------------------------------------
extern "C" void kernel_launch(void* const* d_in, const int* in_sizes, int n_in,
                              void* d_out, int out_size) {
    const float* x   = (const float*)d_in[0];
    const float* fm  = (const float*)d_in[1];
    const float* Wkh = (const float*)d_in[2];
    const float* bkh = (const float*)d_in[3];
    const float* Wko = (const float*)d_in[4];
    const float* bko = (const float*)d_in[5];
    const float* Wqh = (const float*)d_in[6];
    const float* bqh = (const float*)d_in[7];
    const float* Wqo = (const float*)d_in[8];
    const float* bqo = (const float*)d_in[9];
    const float* Wvh = (const float*)d_in[10];
    const float* bvh = (const float*)d_in[11];
    const float* Wvo = (const float*)d_in[12];
    const float* bvo = (const float*)d_in[13];
    const float* pos = (const float*)d_in[14];
    float* out = (float*)d_out;

    cudaFuncSetAttribute(mlp_kernel, cudaFuncAttributeMaxDynamicSharedMemorySize,
                         SMEM_FLOATS * 4);
    cudaFuncSetAttribute(attn_kernel, cudaFuncAttributeMaxDynamicSharedMemorySize,
                         ATTN_SMEM_FLOATS * 4);

    dim3 grid(NROWS / 64, 3);
    mlp_kernel<<<grid, 512, SMEM_FLOATS * 4>>>(x, pos,
        Wkh, bkh, Wko, bko, Wqh, bqh, Wqo, bqo, Wvh, bvh, Wvo, bvo);
    attn_kernel<<<BATCH, 256, ATTN_SMEM_FLOATS * 4>>>(fm, out);
}

// round 3
// speedup vs baseline: 1.0934x; 1.0022x over previous
#include <cuda_runtime.h>
#include <cstdint>
#include <math.h>

#define BATCH 2048
#define NMOL 16
#define CA 512
#define NROWS (BATCH * NMOL)   // 32768
#define K1PAD 80               // 70 padded to 80
#define K2 512

// fp32 scratch for K, Q, V: 3 x 32768 x 512 floats (192 MB)
__device__ float g_scratch[3ULL * NROWS * CA];

// ---------------------------------------------------------------------------
__device__ __forceinline__ unsigned f2tf(float x) {
    unsigned r;
    asm("cvt.rna.tf32.f32 %0, %1;" : "=r"(r) : "f"(x));
    return r;
}

__device__ __forceinline__ void mma_tf32(float d[4], const unsigned a[4], const unsigned b[2]) {
    asm volatile(
        "mma.sync.aligned.m16n8k8.row.col.f32.tf32.tf32.f32 "
        "{%0,%1,%2,%3}, {%4,%5,%6,%7}, {%8,%9}, {%0,%1,%2,%3};\n"
        : "+f"(d[0]), "+f"(d[1]), "+f"(d[2]), "+f"(d[3])
        : "r"(a[0]), "r"(a[1]), "r"(a[2]), "r"(a[3]),
          "r"(b[0]), "r"(b[1]));
}

// pair transform: element k -> position pairing (k, k+4) adjacently within 8-blocks
__device__ __forceinline__ int tp(int k) {
    return (k & ~7) + ((k & 3) << 1) + ((k >> 2) & 1);
}

// ---------------------------------------------------------------------------
// Fused MLP: out = silu(XE @ Wh + bh) @ Wo + bo, 64 rows/CTA, tf32 mma.
// All smem operands stored as pre-converted tf32 bit patterns in
// fragment-paired layouts; strides ≡ 8 (mod 32) words -> conflict-free LDS.64.
// smem: HA[64*520] (XE aliases its head, stride 104) | B2[2][8*1032]
// ---------------------------------------------------------------------------
#define XA_S 104
#define HA_S 520
#define SB   1032
#define B2_OFF (64 * HA_S)                     // 33280 words
#define SMEM_FLOATS (B2_OFF + 2 * 8 * SB)      // 49792 words = 199168 B

__global__ void __launch_bounds__(512, 1)
mlp_kernel(const float* __restrict__ x, const float* __restrict__ pos,
           const float* __restrict__ Wkh, const float* __restrict__ bkh,
           const float* __restrict__ Wko, const float* __restrict__ bko,
           const float* __restrict__ Wqh, const float* __restrict__ bqh,
           const float* __restrict__ Wqo, const float* __restrict__ bqo,
           const float* __restrict__ Wvh, const float* __restrict__ bvh,
           const float* __restrict__ Wvo, const float* __restrict__ bvo)
{
    extern __shared__ unsigned smu[];
    unsigned* HAu = smu;            // paired tf32 H (and XE alias)
    unsigned* B2u = smu + B2_OFF;   // double-buffered paired tf32 W tiles

    const int tid = threadIdx.x;
    const int by  = blockIdx.y;
    const float* Wh = (by == 0) ? Wkh : (by == 1 ? Wqh : Wvh);
    const float* bh = (by == 0) ? bkh : (by == 1 ? bqh : bvh);
    const float* Wo = (by == 0) ? Wko : (by == 1 ? Wqo : Wvo);
    const float* bo = (by == 0) ? bko : (by == 1 ? bqo : bvo);
    float* outg = g_scratch + (size_t)by * NROWS * CA;

    const int row0 = blockIdx.x * 64;

    // ---- XE tile (tf32, paired layout, stride XA_S) ----
    for (int idx = tid; idx < 64 * 80; idx += 512) {
        int r = idx / 80, c = idx - r * 80;
        int rg = row0 + r;
        float v = 0.f;
        if (c < 64)      v = x[(size_t)rg * 64 + c];
        else if (c < 70) v = pos[(rg & 15) * 6 + (c - 64)];
        HAu[r * XA_S + tp(c)] = f2tf(v);
    }

    const int lane = tid & 31;
    const int warp = tid >> 5;
    const int g  = lane >> 2;
    const int t4 = lane & 3;
    const int nw = warp * 32;

    float  acc[4][4][4];
    float4 pf[4];

    // staging geometry (per thread, 2 quad-pairs)
    int pp[2], nn4[2];
    #pragma unroll
    for (int i = 0; i < 2; i++) {
        int f = tid + i * 512;
        pp[i]  = f >> 7;                 // 0..7 pair-row
        nn4[i] = (f & 127) << 2;         // n base (4 cols)
    }

    auto loadPF = [&](int kc, int Krows, const float* W) {
        #pragma unroll
        for (int i = 0; i < 2; i++) {
            int klo = kc * 16 + (pp[i] & 3) + ((pp[i] & 4) << 1);
            int khi = klo + 4;
            pf[2*i]   = (klo < Krows) ? *(const float4*)(W + (size_t)klo * 512 + nn4[i])
                                      : make_float4(0.f,0.f,0.f,0.f);
            pf[2*i+1] = (khi < Krows) ? *(const float4*)(W + (size_t)khi * 512 + nn4[i])
                                      : make_float4(0.f,0.f,0.f,0.f);
        }
    };
    auto storePF = [&](int buf) {
        unsigned* base = B2u + buf * (8 * SB);
        #pragma unroll
        for (int i = 0; i < 2; i++) {
            unsigned* dst = base + pp[i] * SB + (nn4[i] << 1);
            uint4 s0, s1;
            s0.x = f2tf(pf[2*i].x); s0.y = f2tf(pf[2*i+1].x);
            s0.z = f2tf(pf[2*i].y); s0.w = f2tf(pf[2*i+1].y);
            s1.x = f2tf(pf[2*i].z); s1.y = f2tf(pf[2*i+1].z);
            s1.z = f2tf(pf[2*i].w); s1.w = f2tf(pf[2*i+1].w);
            *(uint4*)(dst)     = s0;
            *(uint4*)(dst + 4) = s1;
        }
    };

    auto gemm = [&](const unsigned* Au, int As, int nchunks, int Krows, const float* W) {
        loadPF(0, Krows, W);
        for (int kc = 0; kc < nchunks; ++kc) {
            storePF(kc & 1);
            __syncthreads();
            if (kc + 1 < nchunks) loadPF(kc + 1, Krows, W);
            const unsigned* Br = B2u + (kc & 1) * (8 * SB);
            #pragma unroll
            for (int ks = 0; ks < 2; ++ks) {
                unsigned af[4][4], bf[4][2];
                #pragma unroll
                for (int mt = 0; mt < 4; mt++) {
                    const unsigned* pa = Au + (mt*16 + g) * As + (kc*2 + ks)*8 + (t4 << 1);
                    uint2 lo = *(const uint2*)pa;
                    uint2 hi = *(const uint2*)(pa + 8 * As);
                    af[mt][0] = lo.x; af[mt][1] = hi.x;
                    af[mt][2] = lo.y; af[mt][3] = hi.y;
                }
                #pragma unroll
                for (int nt = 0; nt < 4; nt++) {
                    uint2 b = *(const uint2*)(Br + (t4 + 4*ks) * SB + ((nw + nt*8 + g) << 1));
                    bf[nt][0] = b.x; bf[nt][1] = b.y;
                }
                #pragma unroll
                for (int mt = 0; mt < 4; mt++)
                    #pragma unroll
                    for (int nt = 0; nt < 4; nt++)
                        mma_tf32(acc[mt][nt], af[mt], bf[nt]);
            }
        }
    };

    // ---------------- GEMM1: H = silu(XE @ Wh + bh) ----------------
    #pragma unroll
    for (int i = 0; i < 4; i++)
        #pragma unroll
        for (int j = 0; j < 4; j++)
            #pragma unroll
            for (int q = 0; q < 4; q++) acc[i][j][q] = 0.f;

    gemm(HAu, XA_S, K1PAD / 16, 70, Wh);

    __syncthreads();   // all XE reads done before overwriting region with H

    #pragma unroll
    for (int mt = 0; mt < 4; mt++) {
        #pragma unroll
        for (int nt = 0; nt < 4; nt++) {
            int col = nw + nt * 8 + 2 * t4;
            int r0  = mt * 16 + g;
            float b0 = bh[col], b1 = bh[col + 1];
            float h;
            h = acc[mt][nt][0] + b0; h = h / (1.f + __expf(-h)); HAu[r0 * HA_S + tp(col)]         = f2tf(h);
            h = acc[mt][nt][1] + b1; h = h / (1.f + __expf(-h)); HAu[r0 * HA_S + tp(col + 1)]     = f2tf(h);
            h = acc[mt][nt][2] + b0; h = h / (1.f + __expf(-h)); HAu[(r0+8) * HA_S + tp(col)]     = f2tf(h);
            h = acc[mt][nt][3] + b1; h = h / (1.f + __expf(-h)); HAu[(r0+8) * HA_S + tp(col + 1)] = f2tf(h);
        }
    }
    __syncthreads();

    // ---------------- GEMM2: out = H @ Wo + bo ----------------
    #pragma unroll
    for (int i = 0; i < 4; i++)
        #pragma unroll
        for (int j = 0; j < 4; j++)
            #pragma unroll
            for (int q = 0; q < 4; q++) acc[i][j][q] = 0.f;

    gemm(HAu, HA_S, K2 / 16, 512, Wo);

    #pragma unroll
    for (int mt = 0; mt < 4; mt++) {
        #pragma unroll
        for (int nt = 0; nt < 4; nt++) {
            int col = nw + nt * 8 + 2 * t4;
            int r0  = mt * 16 + g;
            float b0 = bo[col], b1 = bo[col + 1];
            size_t base0 = (size_t)(row0 + r0) * 512 + col;
            size_t base1 = (size_t)(row0 + r0 + 8) * 512 + col;
            outg[base0]     = acc[mt][nt][0] + b0;
            outg[base0 + 1] = acc[mt][nt][1] + b1;
            outg[base1]     = acc[mt][nt][2] + b0;
            outg[base1 + 1] = acc[mt][nt][3] + b1;
        }
    }
}

// ---------------------------------------------------------------------------
// Attention kernel: one CTA per batch element. V prefetched into registers at
// kernel start (hides second DRAM round-trip behind score compute).
// smem: sk[16][516] | sq[16][516] | ws[2048]  (74 KB -> 3 CTAs/SM)
// ---------------------------------------------------------------------------
#define SK_S 516
#define ATTN_SMEM_FLOATS (2 * 16 * SK_S + 2048)

__global__ void __launch_bounds__(256)
attn_kernel(const float* __restrict__ fm, float* __restrict__ out)
{
    extern __shared__ float sm[];
    float* sk = sm;
    float* sq = sm + 16 * SK_S;
    float* ws = sq + 16 * SK_S;

    const int b   = blockIdx.x;
    const int tid = threadIdx.x;
    const float* K = g_scratch + (size_t)b * NMOL * CA;
    const float* Q = g_scratch + (size_t)NROWS * CA + (size_t)b * NMOL * CA;
    const float* V = g_scratch + 2ULL * NROWS * CA + (size_t)b * NMOL * CA;

    // prefetch V into registers (8 x LDG.128)
    float4 v4[8];
    #pragma unroll
    for (int k = 0; k < 8; k++)
        v4[k] = ((const float4*)V)[tid + k * 256];

    // stage K, Q into smem (float4 both directions)
    #pragma unroll
    for (int k = 0; k < 8; k++) {
        int f = tid + k * 256;
        int i = f >> 7, c = (f & 127) << 2;
        *(float4*)(sk + i * SK_S + c) = ((const float4*)K)[f];
        *(float4*)(sq + i * SK_S + c) = ((const float4*)Q)[f];
    }
    __syncthreads();

    // scores: thread owns (i-pair, head c, 4 j's)
    {
        int i2 = tid >> 5;
        int c  = (tid >> 2) & 7;
        int jb = (tid & 3) * 4;
        float a2[2][4];
        #pragma unroll
        for (int ii = 0; ii < 2; ii++)
            #pragma unroll
            for (int jj = 0; jj < 4; jj++) a2[ii][jj] = 0.f;

        const float* k0 = sk + (2 * i2) * SK_S + c * 64;
        const float* k1 = k0 + SK_S;
        #pragma unroll
        for (int a4 = 0; a4 < 16; a4++) {
            float4 kv0 = *(const float4*)(k0 + a4 * 4);
            float4 kv1 = *(const float4*)(k1 + a4 * 4);
            #pragma unroll
            for (int jj = 0; jj < 4; jj++) {
                float4 qv = *(const float4*)(sq + (jb + jj) * SK_S + c * 64 + a4 * 4);
                a2[0][jj] += kv0.x * qv.x + kv0.y * qv.y + kv0.z * qv.z + kv0.w * qv.w;
                a2[1][jj] += kv1.x * qv.x + kv1.y * qv.y + kv1.z * qv.z + kv1.w * qv.w;
            }
        }
        #pragma unroll
        for (int ii = 0; ii < 2; ii++) {
            int i = 2 * i2 + ii;
            float fmi = fm[i];
            #pragma unroll
            for (int jj = 0; jj < 4; jj++) {
                int j = jb + jj;
                float arg = a2[ii][jj] * 0.125f * fmi * fm[j];
                float w;
                if (i == j) w = 0.f;
                else {
                    float sp = (arg > 20.f) ? arg : log1pf(__expf(arg));
                    w = sp + 1e-5f;
                }
                ws[(i * 8 + c) * 16 + j] = w;
            }
        }
    }
    __syncthreads();

    // normalize over j (threads 0..127) ; concurrently store V regs -> sk
    if (tid < 128) {
        float* row = ws + tid * 16;
        float s = 0.f;
        #pragma unroll
        for (int j = 0; j < 16; j++) s += row[j];
        float inv = 1.f / s;
        #pragma unroll
        for (int j = 0; j < 16; j++) row[j] = row[j] * inv * fm[j];
    }
    #pragma unroll
    for (int k = 0; k < 8; k++) {
        int f = tid + k * 256;
        int i = f >> 7, c = (f & 127) << 2;
        *(float4*)(sk + i * SK_S + c) = v4[k];
    }
    __syncthreads();

    // combine: thread owns (d, 4 i's)
    {
        int d  = tid & 63;
        int ib = tid >> 6;
        float a4[4] = {0.f, 0.f, 0.f, 0.f};
        #pragma unroll
        for (int c = 0; c < 8; c++) {
            #pragma unroll
            for (int j = 0; j < 16; j++) {
                float vv = sk[j * SK_S + c * 64 + d];
                #pragma unroll
                for (int ii = 0; ii < 4; ii++) {
                    int i = ii * 4 + ib;
                    a4[ii] += ws[(i * 8 + c) * 16 + j] * vv;
                }
            }
        }
        #pragma unroll
        for (int ii = 0; ii < 4; ii++) {
            int i = ii * 4 + ib;
            out[(size_t)b * 1024 + i * 64 + d] = a4[ii];
        }
    }
}

// ---------------------------------------------------------------------------
extern "C" void kernel_launch(void* const* d_in, const int* in_sizes, int n_in,
                              void* d_out, int out_size) {
    const float* x   = (const float*)d_in[0];
    const float* fm  = (const float*)d_in[1];
    const float* Wkh = (const float*)d_in[2];
    const float* bkh = (const float*)d_in[3];
    const float* Wko = (const float*)d_in[4];
    const float* bko = (const float*)d_in[5];
    const float* Wqh = (const float*)d_in[6];
    const float* bqh = (const float*)d_in[7];
    const float* Wqo = (const float*)d_in[8];
    const float* bqo = (const float*)d_in[9];
    const float* Wvh = (const float*)d_in[10];
    const float* bvh = (const float*)d_in[11];
    const float* Wvo = (const float*)d_in[12];
    const float* bvo = (const float*)d_in[13];
    const float* pos = (const float*)d_in[14];
    float* out = (float*)d_out;

    cudaFuncSetAttribute(mlp_kernel, cudaFuncAttributeMaxDynamicSharedMemorySize,
                         SMEM_FLOATS * 4);
    cudaFuncSetAttribute(attn_kernel, cudaFuncAttributeMaxDynamicSharedMemorySize,
                         ATTN_SMEM_FLOATS * 4);

    dim3 grid(NROWS / 64, 3);
    mlp_kernel<<<grid, 512, SMEM_FLOATS * 4>>>(x, pos,
        Wkh, bkh, Wko, bko, Wqh, bqh, Wqo, bqo, Wvh, bvh, Wvo, bvo);
    attn_kernel<<<BATCH, 256, ATTN_SMEM_FLOATS * 4>>>(fm, out);
}

// round 5
// speedup vs baseline: 1.5807x; 1.4457x over previous
#include <cuda_runtime.h>
#include <cuda_fp16.h>
#include <cstdint>
#include <math.h>

#define BATCH 2048
#define NMOL 16
#define CA 512
#define NROWS (BATCH * NMOL)   // 32768
#define NCH 37                 // 5 chunks (GEMM1, k=80) + 32 chunks (GEMM2, k=512)

// fp32 scratch for K, Q, V (192 MB) + prepped fp16 weight stages
__device__ float g_scratch[3ULL * NROWS * CA];
__device__ uint4 g_wstage[3 * NCH * 1032];   // 16512 B per stage

// ---------------------------------------------------------------------------
__device__ __forceinline__ uint32_t smem_u32(const void* p) {
    uint32_t a;
    asm("{ .reg .u64 t; cvta.to.shared.u64 t, %1; cvt.u32.u64 %0, t; }" : "=r"(a) : "l"(p));
    return a;
}
__device__ __forceinline__ void cpa16(uint32_t dst, const void* src) {
    asm volatile("cp.async.cg.shared.global [%0], [%1], 16;" :: "r"(dst), "l"(src));
}
#define CPA_COMMIT() asm volatile("cp.async.commit_group;" ::: "memory")

__device__ __forceinline__ void mma_f16(float d[4], const unsigned a[4], const unsigned b[2]) {
    asm volatile(
        "mma.sync.aligned.m16n8k16.row.col.f32.f16.f16.f32 "
        "{%0,%1,%2,%3}, {%4,%5,%6,%7}, {%8,%9}, {%0,%1,%2,%3};\n"
        : "+f"(d[0]), "+f"(d[1]), "+f"(d[2]), "+f"(d[3])
        : "r"(a[0]), "r"(a[1]), "r"(a[2]), "r"(a[3]),
          "r"(b[0]), "r"(b[1]));
}

// ---------------------------------------------------------------------------
// Prologue: convert + transpose weights into fp16 stage blobs matching the
// smem layout: stage = [t4][n][e], halves idx = t4*2064 + n*4 + e,
// where thread t4 owns k in {2t4, 2t4+1, 2t4+8, 2t4+9} (e = 0..3).
// ---------------------------------------------------------------------------
__global__ void __launch_bounds__(256)
prep_weights(const float* __restrict__ Wkh, const float* __restrict__ Wko,
             const float* __restrict__ Wqh, const float* __restrict__ Wqo,
             const float* __restrict__ Wvh, const float* __restrict__ Wvo)
{
    const int br = blockIdx.x / NCH;
    const int s  = blockIdx.x % NCH;
    const float* Wh = (br == 0) ? Wkh : (br == 1 ? Wqh : Wvh);
    const float* Wo = (br == 0) ? Wko : (br == 1 ? Wqo : Wvo);

    const float* W; int kbase, Krows;
    if (s < 5) { W = Wh; kbase = s * 16;       Krows = 70;  }
    else       { W = Wo; kbase = (s - 5) * 16; Krows = 512; }

    unsigned short* dst = (unsigned short*)&g_wstage[((size_t)br * NCH + s) * 1032];
    for (int idx = threadIdx.x; idx < 8192; idx += 256) {
        int kl = idx >> 9;        // 0..15
        int n  = idx & 511;
        int kg = kbase + kl;
        float v = (kg < Krows) ? W[(size_t)kg * 512 + n] : 0.f;
        int t4 = (kl & 7) >> 1;
        int e  = ((kl >> 3) << 1) | (kl & 1);
        dst[t4 * 2064 + n * 4 + e] = __half_as_ushort(__float2half_rn(v));
    }
}

// ---------------------------------------------------------------------------
// Fused fp16 MLP: 64 rows/CTA, grid (512, 3), 512 threads.
// smem bytes: XE [0, 10240)  (64 rows x 80 halves, stride 160 B)
//             H  [10240, 77824)  (64 x 528 halves, stride 1056 B)
//             stages [77824, 127360)  3 x 16512 B
// All strides ≡ 32 (mod 128) -> conflict-free fragment LDS.64.
// ---------------------------------------------------------------------------
#define XE_OFF    0
#define H_OFF     10240
#define STAGE_OFF 77824
#define SMEM_BYTES (STAGE_OFF + 3 * 16512)   // 127360

__global__ void __launch_bounds__(512, 1)
mlp_kernel(const float* __restrict__ x, const float* __restrict__ pos,
           const float* __restrict__ bkh, const float* __restrict__ bko,
           const float* __restrict__ bqh, const float* __restrict__ bqo,
           const float* __restrict__ bvh, const float* __restrict__ bvo)
{
    extern __shared__ char smem[];
    const uint32_t smem_base = smem_u32(smem);
    const int tid  = threadIdx.x;
    const int by   = blockIdx.y;
    const int row0 = blockIdx.x * 64;

    const float* bh = (by == 0) ? bkh : (by == 1 ? bqh : bvh);
    const float* bo = (by == 0) ? bko : (by == 1 ? bqo : bvo);
    float* outg = g_scratch + (size_t)by * NROWS * CA;
    const uint4* wbase = g_wstage + (size_t)by * NCH * 1032;

    // ---- build XE (fp16, pair-interleaved k order) ----
    {
        __half* XE = (__half*)(smem + XE_OFF);
        for (int idx = tid; idx < 64 * 80; idx += 512) {
            int r = idx / 80, c = idx - r * 80;
            int rg = row0 + r;
            float v = 0.f;
            if (c < 64)      v = x[(size_t)rg * 64 + c];
            else if (c < 70) v = pos[(rg & 15) * 6 + (c - 64)];
            int cl = c & 15;
            int p16 = ((cl & 6) << 1) + ((cl >> 3) << 1) + (cl & 1);
            XE[r * 80 + (c >> 4) * 16 + p16] = __float2half_rn(v);
        }
    }

    const int lane = tid & 31;
    const int warp = tid >> 5;       // 16 warps, each owns 32 N cols
    const int g  = lane >> 2;
    const int t4 = lane & 3;
    const int nw = warp * 32;

    auto issue_load = [&](int s) {
        const uint4* src = wbase + (size_t)s * 1032;
        uint32_t dst = smem_base + STAGE_OFF + (s % 3) * 16512;
        cpa16(dst + tid * 16, src + tid);
        cpa16(dst + (tid + 512) * 16, src + tid + 512);
        if (tid < 8) cpa16(dst + (tid + 1024) * 16, src + tid + 1024);
        CPA_COMMIT();
    };

    float acc[4][4][4];
    #pragma unroll
    for (int i = 0; i < 4; i++)
        #pragma unroll
        for (int j = 0; j < 4; j++)
            #pragma unroll
            for (int q = 0; q < 4; q++) acc[i][j][q] = 0.f;

    issue_load(0);
    issue_load(1);
    __syncthreads();   // XE visible

    for (int s = 0; s < NCH; ++s) {
        if (s == 5) {
            // ---- epilogue1: H = silu(D1 + bh), stored fp16 pair-interleaved ----
            __half* H = (__half*)(smem + H_OFF);
            #pragma unroll
            for (int mt = 0; mt < 4; mt++) {
                #pragma unroll
                for (int nt = 0; nt < 4; nt++) {
                    int col = nw + nt * 8 + 2 * t4;
                    int r0  = mt * 16 + g;
                    float b0 = bh[col], b1 = bh[col + 1];
                    int cl = col & 15;
                    int p16 = ((cl & 6) << 1) + ((cl >> 3) << 1);
                    int off = r0 * 528 + (col >> 4) * 16 + p16;
                    float h0 = acc[mt][nt][0] + b0; h0 = h0 / (1.f + __expf(-h0));
                    float h1 = acc[mt][nt][1] + b1; h1 = h1 / (1.f + __expf(-h1));
                    float h2 = acc[mt][nt][2] + b0; h2 = h2 / (1.f + __expf(-h2));
                    float h3 = acc[mt][nt][3] + b1; h3 = h3 / (1.f + __expf(-h3));
                    *(__half2*)(H + off)            = __floats2half2_rn(h0, h1);
                    *(__half2*)(H + off + 8 * 528)  = __floats2half2_rn(h2, h3);
                    acc[mt][nt][0] = 0.f; acc[mt][nt][1] = 0.f;
                    acc[mt][nt][2] = 0.f; acc[mt][nt][3] = 0.f;
                }
            }
            __syncthreads();
        }

        if (s < NCH - 1) asm volatile("cp.async.wait_group 1;" ::: "memory");
        else             asm volatile("cp.async.wait_group 0;" ::: "memory");
        __syncthreads();

        if (s + 2 < NCH) issue_load(s + 2);

        const __half* Abase; int SA, coff;
        if (s < 5) { Abase = (const __half*)(smem + XE_OFF); SA = 80;  coff = s * 16; }
        else       { Abase = (const __half*)(smem + H_OFF);  SA = 528; coff = (s - 5) * 16; }
        const __half* Bbuf = (const __half*)(smem + STAGE_OFF + (s % 3) * 16512);

        unsigned af[4][4], bf[4][2];
        #pragma unroll
        for (int mt = 0; mt < 4; mt++) {
            const __half* p0 = Abase + (mt * 16 + g) * SA + coff + t4 * 4;
            uint2 lo = *(const uint2*)p0;
            uint2 hi = *(const uint2*)(p0 + 8 * SA);
            af[mt][0] = lo.x; af[mt][2] = lo.y;
            af[mt][1] = hi.x; af[mt][3] = hi.y;
        }
        #pragma unroll
        for (int nt = 0; nt < 4; nt++) {
            uint2 b = *(const uint2*)(Bbuf + t4 * 2064 + (nw + nt * 8 + g) * 4);
            bf[nt][0] = b.x; bf[nt][1] = b.y;
        }
        #pragma unroll
        for (int mt = 0; mt < 4; mt++)
            #pragma unroll
            for (int nt = 0; nt < 4; nt++)
                mma_f16(acc[mt][nt], af[mt], bf[nt]);
    }

    // ---- epilogue2: out = D2 + bo (coalesces into 32B sectors per warp) ----
    #pragma unroll
    for (int mt = 0; mt < 4; mt++) {
        #pragma unroll
        for (int nt = 0; nt < 4; nt++) {
            int col = nw + nt * 8 + 2 * t4;
            int r0  = mt * 16 + g;
            float b0 = bo[col], b1 = bo[col + 1];
            size_t base0 = (size_t)(row0 + r0) * 512 + col;
            size_t base1 = (size_t)(row0 + r0 + 8) * 512 + col;
            outg[base0]     = acc[mt][nt][0] + b0;
            outg[base0 + 1] = acc[mt][nt][1] + b1;
            outg[base1]     = acc[mt][nt][2] + b0;
            outg[base1 + 1] = acc[mt][nt][3] + b1;
        }
    }
}

// ---------------------------------------------------------------------------
// Attention kernel (unchanged, ~120 us)
// ---------------------------------------------------------------------------
#define SK_S 516
#define ATTN_SMEM_FLOATS (2 * 16 * SK_S + 2048)

__global__ void __launch_bounds__(256)
attn_kernel(const float* __restrict__ fm, float* __restrict__ out)
{
    extern __shared__ float sm[];
    float* sk = sm;
    float* sq = sm + 16 * SK_S;
    float* ws = sq + 16 * SK_S;

    const int b   = blockIdx.x;
    const int tid = threadIdx.x;
    const float* K = g_scratch + (size_t)b * NMOL * CA;
    const float* Q = g_scratch + (size_t)NROWS * CA + (size_t)b * NMOL * CA;
    const float* V = g_scratch + 2ULL * NROWS * CA + (size_t)b * NMOL * CA;

    float4 v4[8];
    #pragma unroll
    for (int k = 0; k < 8; k++)
        v4[k] = ((const float4*)V)[tid + k * 256];

    #pragma unroll
    for (int k = 0; k < 8; k++) {
        int f = tid + k * 256;
        int i = f >> 7, c = (f & 127) << 2;
        *(float4*)(sk + i * SK_S + c) = ((const float4*)K)[f];
        *(float4*)(sq + i * SK_S + c) = ((const float4*)Q)[f];
    }
    __syncthreads();

    {
        int i2 = tid >> 5;
        int c  = (tid >> 2) & 7;
        int jb = (tid & 3) * 4;
        float a2[2][4];
        #pragma unroll
        for (int ii = 0; ii < 2; ii++)
            #pragma unroll
            for (int jj = 0; jj < 4; jj++) a2[ii][jj] = 0.f;

        const float* k0 = sk + (2 * i2) * SK_S + c * 64;
        const float* k1 = k0 + SK_S;
        #pragma unroll
        for (int a4 = 0; a4 < 16; a4++) {
            float4 kv0 = *(const float4*)(k0 + a4 * 4);
            float4 kv1 = *(const float4*)(k1 + a4 * 4);
            #pragma unroll
            for (int jj = 0; jj < 4; jj++) {
                float4 qv = *(const float4*)(sq + (jb + jj) * SK_S + c * 64 + a4 * 4);
                a2[0][jj] += kv0.x * qv.x + kv0.y * qv.y + kv0.z * qv.z + kv0.w * qv.w;
                a2[1][jj] += kv1.x * qv.x + kv1.y * qv.y + kv1.z * qv.z + kv1.w * qv.w;
            }
        }
        #pragma unroll
        for (int ii = 0; ii < 2; ii++) {
            int i = 2 * i2 + ii;
            float fmi = fm[i];
            #pragma unroll
            for (int jj = 0; jj < 4; jj++) {
                int j = jb + jj;
                float arg = a2[ii][jj] * 0.125f * fmi * fm[j];
                float w;
                if (i == j) w = 0.f;
                else {
                    float sp = (arg > 20.f) ? arg : log1pf(__expf(arg));
                    w = sp + 1e-5f;
                }
                ws[(i * 8 + c) * 16 + j] = w;
            }
        }
    }
    __syncthreads();

    if (tid < 128) {
        float* row = ws + tid * 16;
        float s = 0.f;
        #pragma unroll
        for (int j = 0; j < 16; j++) s += row[j];
        float inv = 1.f / s;
        #pragma unroll
        for (int j = 0; j < 16; j++) row[j] = row[j] * inv * fm[j];
    }
    #pragma unroll
    for (int k = 0; k < 8; k++) {
        int f = tid + k * 256;
        int i = f >> 7, c = (f & 127) << 2;
        *(float4*)(sk + i * SK_S + c) = v4[k];
    }
    __syncthreads();

    {
        int d  = tid & 63;
        int ib = tid >> 6;
        float a4[4] = {0.f, 0.f, 0.f, 0.f};
        #pragma unroll
        for (int c = 0; c < 8; c++) {
            #pragma unroll
            for (int j = 0; j < 16; j++) {
                float vv = sk[j * SK_S + c * 64 + d];
                #pragma unroll
                for (int ii = 0; ii < 4; ii++) {
                    int i = ii * 4 + ib;
                    a4[ii] += ws[(i * 8 + c) * 16 + j] * vv;
                }
            }
        }
        #pragma unroll
        for (int ii = 0; ii < 4; ii++) {
            int i = ii * 4 + ib;
            out[(size_t)b * 1024 + i * 64 + d] = a4[ii];
        }
    }
}

// trailing no-op so ncu -s 5 -c 1 lands on mlp_kernel (launch pattern:
// prep, mlp, attn, pad | prep, MLP <- captured)
__global__ void pad_kernel() {}

// ---------------------------------------------------------------------------
extern "C" void kernel_launch(void* const* d_in, const int* in_sizes, int n_in,
                              void* d_out, int out_size) {
    const float* x   = (const float*)d_in[0];
    const float* fm  = (const float*)d_in[1];
    const float* Wkh = (const float*)d_in[2];
    const float* bkh = (const float*)d_in[3];
    const float* Wko = (const float*)d_in[4];
    const float* bko = (const float*)d_in[5];
    const float* Wqh = (const float*)d_in[6];
    const float* bqh = (const float*)d_in[7];
    const float* Wqo = (const float*)d_in[8];
    const float* bqo = (const float*)d_in[9];
    const float* Wvh = (const float*)d_in[10];
    const float* bvh = (const float*)d_in[11];
    const float* Wvo = (const float*)d_in[12];
    const float* bvo = (const float*)d_in[13];
    const float* pos = (const float*)d_in[14];
    float* out = (float*)d_out;

    cudaFuncSetAttribute(mlp_kernel, cudaFuncAttributeMaxDynamicSharedMemorySize,
                         SMEM_BYTES);
    cudaFuncSetAttribute(attn_kernel, cudaFuncAttributeMaxDynamicSharedMemorySize,
                         ATTN_SMEM_FLOATS * 4);

    prep_weights<<<3 * NCH, 256>>>(Wkh, Wko, Wqh, Wqo, Wvh, Wvo);

    dim3 grid(NROWS / 64, 3);
    mlp_kernel<<<grid, 512, SMEM_BYTES>>>(x, pos, bkh, bko, bqh, bqo, bvh, bvo);

    attn_kernel<<<BATCH, 256, ATTN_SMEM_FLOATS * 4>>>(fm, out);

    pad_kernel<<<1, 32>>>();
}

// round 7
// speedup vs baseline: 2.0361x; 1.2880x over previous
#include <cuda_runtime.h>
#include <cuda_fp16.h>
#include <cstdint>
#include <math.h>

#define BATCH 2048
#define NMOL 16
#define CA 512
#define NROWS (BATCH * NMOL)   // 32768
#define NCH 37                 // 5 chunks (GEMM1, k=80) + 32 chunks (GEMM2, k=512)

// fp16 scratch for K, Q, V (96 MB) + prepped fp16 weight stages
__device__ __half g_scratch_h[3ULL * NROWS * CA];
__device__ uint4 g_wstage[3 * NCH * 1032];   // 16512 B per stage

// ---------------------------------------------------------------------------
__device__ __forceinline__ uint32_t smem_u32(const void* p) {
    uint32_t a;
    asm("{ .reg .u64 t; cvta.to.shared.u64 t, %1; cvt.u32.u64 %0, t; }" : "=r"(a) : "l"(p));
    return a;
}
__device__ __forceinline__ void cpa16(uint32_t dst, const void* src) {
    asm volatile("cp.async.cg.shared.global [%0], [%1], 16;" :: "r"(dst), "l"(src));
}
#define CPA_COMMIT() asm volatile("cp.async.commit_group;" ::: "memory")

__device__ __forceinline__ void mma_f16(float d[4], const unsigned a[4], const unsigned b[2]) {
    asm volatile(
        "mma.sync.aligned.m16n8k16.row.col.f32.f16.f16.f32 "
        "{%0,%1,%2,%3}, {%4,%5,%6,%7}, {%8,%9}, {%0,%1,%2,%3};\n"
        : "+f"(d[0]), "+f"(d[1]), "+f"(d[2]), "+f"(d[3])
        : "r"(a[0]), "r"(a[1]), "r"(a[2]), "r"(a[3]),
          "r"(b[0]), "r"(b[1]));
}

// bit-cast half2 -> unsigned (no such intrinsic exists; reinterpret)
__device__ __forceinline__ unsigned h2u(__half2 h) {
    return *reinterpret_cast<unsigned*>(&h);
}

// pair-interleave within a 16-group: k -> ((k&6)<<1) + ((k>>3)<<1) + (k&1)
__device__ __forceinline__ int p16(int k) {
    return ((k & 6) << 1) + (((k >> 3) & 1) << 1) + (k & 1);
}

// ---------------------------------------------------------------------------
// Prologue: weights -> fp16 stage blobs, layout [t4][n][e], e: k in
// {2t4, 2t4+1, 2t4+8, 2t4+9}
// ---------------------------------------------------------------------------
__global__ void __launch_bounds__(256)
prep_weights(const float* __restrict__ Wkh, const float* __restrict__ Wko,
             const float* __restrict__ Wqh, const float* __restrict__ Wqo,
             const float* __restrict__ Wvh, const float* __restrict__ Wvo)
{
    const int br = blockIdx.x / NCH;
    const int s  = blockIdx.x % NCH;
    const float* Wh = (br == 0) ? Wkh : (br == 1 ? Wqh : Wvh);
    const float* Wo = (br == 0) ? Wko : (br == 1 ? Wqo : Wvo);

    const float* W; int kbase, Krows;
    if (s < 5) { W = Wh; kbase = s * 16;       Krows = 70;  }
    else       { W = Wo; kbase = (s - 5) * 16; Krows = 512; }

    unsigned short* dst = (unsigned short*)&g_wstage[((size_t)br * NCH + s) * 1032];
    for (int idx = threadIdx.x; idx < 8192; idx += 256) {
        int kl = idx >> 9;        // 0..15
        int n  = idx & 511;
        int kg = kbase + kl;
        float v = (kg < Krows) ? W[(size_t)kg * 512 + n] : 0.f;
        int t4 = (kl & 7) >> 1;
        int e  = ((kl >> 3) << 1) | (kl & 1);
        dst[t4 * 2064 + n * 4 + e] = __half_as_ushort(__float2half_rn(v));
    }
}

// ---------------------------------------------------------------------------
// Fused fp16 MLP (as R5) with fp16 half2 epilogue2 to scratch.
// ---------------------------------------------------------------------------
#define XE_OFF    0
#define H_OFF     10240
#define STAGE_OFF 77824
#define SMEM_BYTES (STAGE_OFF + 3 * 16512)   // 127360

__global__ void __launch_bounds__(512, 1)
mlp_kernel(const float* __restrict__ x, const float* __restrict__ pos,
           const float* __restrict__ bkh, const float* __restrict__ bko,
           const float* __restrict__ bqh, const float* __restrict__ bqo,
           const float* __restrict__ bvh, const float* __restrict__ bvo)
{
    extern __shared__ char smem[];
    const uint32_t smem_base = smem_u32(smem);
    const int tid  = threadIdx.x;
    const int by   = blockIdx.y;
    const int row0 = blockIdx.x * 64;

    const float* bh = (by == 0) ? bkh : (by == 1 ? bqh : bvh);
    const float* bo = (by == 0) ? bko : (by == 1 ? bqo : bvo);
    __half* outh = g_scratch_h + (size_t)by * NROWS * CA;
    const uint4* wbase = g_wstage + (size_t)by * NCH * 1032;

    // ---- build XE (fp16, pair-interleaved k order) ----
    {
        __half* XE = (__half*)(smem + XE_OFF);
        for (int idx = tid; idx < 64 * 80; idx += 512) {
            int r = idx / 80, c = idx - r * 80;
            int rg = row0 + r;
            float v = 0.f;
            if (c < 64)      v = x[(size_t)rg * 64 + c];
            else if (c < 70) v = pos[(rg & 15) * 6 + (c - 64)];
            XE[r * 80 + (c >> 4) * 16 + p16(c & 15)] = __float2half_rn(v);
        }
    }

    const int lane = tid & 31;
    const int warp = tid >> 5;       // 16 warps, each owns 32 N cols
    const int g  = lane >> 2;
    const int t4 = lane & 3;
    const int nw = warp * 32;

    auto issue_load = [&](int s) {
        const uint4* src = wbase + (size_t)s * 1032;
        uint32_t dst = smem_base + STAGE_OFF + (s % 3) * 16512;
        cpa16(dst + tid * 16, src + tid);
        cpa16(dst + (tid + 512) * 16, src + tid + 512);
        if (tid < 8) cpa16(dst + (tid + 1024) * 16, src + tid + 1024);
        CPA_COMMIT();
    };

    float acc[4][4][4];
    #pragma unroll
    for (int i = 0; i < 4; i++)
        #pragma unroll
        for (int j = 0; j < 4; j++)
            #pragma unroll
            for (int q = 0; q < 4; q++) acc[i][j][q] = 0.f;

    issue_load(0);
    issue_load(1);
    __syncthreads();   // XE visible

    for (int s = 0; s < NCH; ++s) {
        if (s == 5) {
            // ---- epilogue1: H = silu(D1 + bh), fp16 pair-interleaved ----
            __half* H = (__half*)(smem + H_OFF);
            #pragma unroll
            for (int mt = 0; mt < 4; mt++) {
                #pragma unroll
                for (int nt = 0; nt < 4; nt++) {
                    int col = nw + nt * 8 + 2 * t4;
                    int r0  = mt * 16 + g;
                    float b0 = bh[col], b1 = bh[col + 1];
                    int cl = col & 15;
                    int pp = ((cl & 6) << 1) + ((cl >> 3) << 1);
                    int off = r0 * 528 + (col >> 4) * 16 + pp;
                    float h0 = acc[mt][nt][0] + b0; h0 = h0 / (1.f + __expf(-h0));
                    float h1 = acc[mt][nt][1] + b1; h1 = h1 / (1.f + __expf(-h1));
                    float h2 = acc[mt][nt][2] + b0; h2 = h2 / (1.f + __expf(-h2));
                    float h3 = acc[mt][nt][3] + b1; h3 = h3 / (1.f + __expf(-h3));
                    *(__half2*)(H + off)            = __floats2half2_rn(h0, h1);
                    *(__half2*)(H + off + 8 * 528)  = __floats2half2_rn(h2, h3);
                    acc[mt][nt][0] = 0.f; acc[mt][nt][1] = 0.f;
                    acc[mt][nt][2] = 0.f; acc[mt][nt][3] = 0.f;
                }
            }
            __syncthreads();
        }

        if (s < NCH - 1) asm volatile("cp.async.wait_group 1;" ::: "memory");
        else             asm volatile("cp.async.wait_group 0;" ::: "memory");
        __syncthreads();

        if (s + 2 < NCH) issue_load(s + 2);

        const __half* Abase; int SA, coff;
        if (s < 5) { Abase = (const __half*)(smem + XE_OFF); SA = 80;  coff = s * 16; }
        else       { Abase = (const __half*)(smem + H_OFF);  SA = 528; coff = (s - 5) * 16; }
        const __half* Bbuf = (const __half*)(smem + STAGE_OFF + (s % 3) * 16512);

        unsigned af[4][4], bf[4][2];
        #pragma unroll
        for (int mt = 0; mt < 4; mt++) {
            const __half* p0 = Abase + (mt * 16 + g) * SA + coff + t4 * 4;
            uint2 lo = *(const uint2*)p0;
            uint2 hi = *(const uint2*)(p0 + 8 * SA);
            af[mt][0] = lo.x; af[mt][2] = lo.y;
            af[mt][1] = hi.x; af[mt][3] = hi.y;
        }
        #pragma unroll
        for (int nt = 0; nt < 4; nt++) {
            uint2 b = *(const uint2*)(Bbuf + t4 * 2064 + (nw + nt * 8 + g) * 4);
            bf[nt][0] = b.x; bf[nt][1] = b.y;
        }
        #pragma unroll
        for (int mt = 0; mt < 4; mt++)
            #pragma unroll
            for (int nt = 0; nt < 4; nt++)
                mma_f16(acc[mt][nt], af[mt], bf[nt]);
    }

    // ---- epilogue2: scratch(fp16) = D2 + bo ----
    #pragma unroll
    for (int mt = 0; mt < 4; mt++) {
        #pragma unroll
        for (int nt = 0; nt < 4; nt++) {
            int col = nw + nt * 8 + 2 * t4;
            int r0  = mt * 16 + g;
            float b0 = bo[col], b1 = bo[col + 1];
            *(__half2*)(outh + (size_t)(row0 + r0) * 512 + col)
                = __floats2half2_rn(acc[mt][nt][0] + b0, acc[mt][nt][1] + b1);
            *(__half2*)(outh + (size_t)(row0 + r0 + 8) * 512 + col)
                = __floats2half2_rn(acc[mt][nt][2] + b0, acc[mt][nt][3] + b1);
        }
    }
}

// ---------------------------------------------------------------------------
// Attention, fp16 mma: 1 CTA / batch elem, 256 thr, warp = head.
// smem (halves): Ks [8][16][72] @0 | Qs @9216 | Vt [8][64][24] @18432
// reduce buffer (float [8][16][68]) overlays Ks/Qs region.
// ---------------------------------------------------------------------------
#define KS_OFF 0
#define QS_OFF 9216
#define VT_OFF 18432
#define ATTN_SMEM_BYTES ((VT_OFF + 12288) * 2)   // 61440

__global__ void __launch_bounds__(256)
attn_kernel(const float* __restrict__ fm, float* __restrict__ out)
{
    extern __shared__ char smem[];
    __half* smh = (__half*)smem;
    float*  fbuf = (float*)smem;

    const int b    = blockIdx.x;
    const int tid  = threadIdx.x;
    const int warp = tid >> 5;       // head c
    const int lane = tid & 31;
    const int g    = lane >> 2;
    const int t4   = lane & 3;

    const unsigned* kg32 = (const unsigned*)g_scratch_h + (size_t)b * 4096;
    const unsigned* qg32 = kg32 + 8388608;    // NROWS*CA/2
    const unsigned* vg32 = kg32 + 16777216;

    // ---- stage K, Q (pair-interleaved k) and V (transposed, interleaved j) --
    #pragma unroll
    for (int it = 0; it < 16; it++) {
        int f = tid + it * 256;              // uint index, 4096 per tensor
        int i = f >> 8, rem = f & 255;
        int c = rem >> 5, m = rem & 31;      // halves a=2m,2m+1
        int a = 2 * m;
        int koff = (a >> 4) * 16 + p16(a & 15);
        *(unsigned*)(smh + KS_OFF + c * 1152 + i * 72 + koff) = kg32[f];
        *(unsigned*)(smh + QS_OFF + c * 1152 + i * 72 + koff) = qg32[f];
        unsigned v = vg32[f];
        int pj = p16(i);
        smh[VT_OFF + c * 1536 + a * 24 + pj]       = __ushort_as_half((unsigned short)(v & 0xFFFF));
        smh[VT_OFF + c * 1536 + (a + 1) * 24 + pj] = __ushort_as_half((unsigned short)(v >> 16));
    }
    __syncthreads();

    // ---- scores: D[i][j] = K_c . Q_c  (m16n16k64) ----
    float d0[4] = {0.f, 0.f, 0.f, 0.f};   // j tile 0..7
    float d1[4] = {0.f, 0.f, 0.f, 0.f};   // j tile 8..15
    const __half* Kc = smh + KS_OFF + warp * 1152;
    const __half* Qc = smh + QS_OFF + warp * 1152;
    #pragma unroll
    for (int kc = 0; kc < 4; kc++) {
        unsigned af[4];
        uint2 lo = *(const uint2*)(Kc + g * 72 + kc * 16 + t4 * 4);
        uint2 hi = *(const uint2*)(Kc + (g + 8) * 72 + kc * 16 + t4 * 4);
        af[0] = lo.x; af[1] = hi.x; af[2] = lo.y; af[3] = hi.y;
        uint2 q0 = *(const uint2*)(Qc + g * 72 + kc * 16 + t4 * 4);
        uint2 q1 = *(const uint2*)(Qc + (g + 8) * 72 + kc * 16 + t4 * 4);
        unsigned b0[2] = {q0.x, q0.y};
        unsigned b1[2] = {q1.x, q1.y};
        mma_f16(d0, af, b0);
        mma_f16(d1, af, b1);
    }

    // ---- softplus weights + row-normalize (registers + quad shuffles) ----
    const float fr0 = __ldg(&fm[g]);
    const float fr1 = __ldg(&fm[g + 8]);
    float w0[4], w1[4];
    #pragma unroll
    for (int e = 0; e < 4; e++) {
        int row = (e >= 2) ? (g + 8) : g;
        float frow = (e >= 2) ? fr1 : fr0;
        int j0 = 2 * t4 + (e & 1);
        int j1 = j0 + 8;
        float fj0 = __ldg(&fm[j0]);
        float fj1 = __ldg(&fm[j1]);
        float a0 = d0[e] * 0.125f * frow * fj0;
        float a1 = d1[e] * 0.125f * frow * fj1;
        float s0 = (a0 > 20.f) ? a0 : log1pf(__expf(a0));
        float s1 = (a1 > 20.f) ? a1 : log1pf(__expf(a1));
        w0[e] = (row == j0) ? 0.f : (s0 + 1e-5f);
        w1[e] = (row == j1) ? 0.f : (s1 + 1e-5f);
    }
    float s0 = w0[0] + w0[1] + w1[0] + w1[1];   // row g
    float s1 = w0[2] + w0[3] + w1[2] + w1[3];   // row g+8
    s0 += __shfl_xor_sync(0xffffffffu, s0, 1);
    s0 += __shfl_xor_sync(0xffffffffu, s0, 2);
    s1 += __shfl_xor_sync(0xffffffffu, s1, 1);
    s1 += __shfl_xor_sync(0xffffffffu, s1, 2);
    float i0 = 1.f / s0, i1 = 1.f / s1;
    #pragma unroll
    for (int e = 0; e < 4; e++) {
        int j0 = 2 * t4 + (e & 1);
        float inv = (e >= 2) ? i1 : i0;
        w0[e] = w0[e] * inv * __ldg(&fm[j0]);
        w1[e] = w1[e] * inv * __ldg(&fm[j0 + 8]);
    }

    // w -> fp16 A fragment for combine (rows i, k = j)
    unsigned aw[4];
    aw[0] = h2u(__floats2half2_rn(w0[0], w0[1]));   // (g,   j 2t4,2t4+1)
    aw[1] = h2u(__floats2half2_rn(w0[2], w0[3]));   // (g+8, j 2t4,2t4+1)
    aw[2] = h2u(__floats2half2_rn(w1[0], w1[1]));   // (g,   j +8)
    aw[3] = h2u(__floats2half2_rn(w1[2], w1[3]));   // (g+8, j +8)

    // ---- combine: O_c = W @ V  (m16n64k16) ----
    float o[8][4];
    const __half* Vc = smh + VT_OFF + warp * 1536;
    #pragma unroll
    for (int nt = 0; nt < 8; nt++) {
        o[nt][0] = o[nt][1] = o[nt][2] = o[nt][3] = 0.f;
        uint2 vb = *(const uint2*)(Vc + (nt * 8 + g) * 24 + t4 * 4);
        unsigned bb[2] = {vb.x, vb.y};
        mma_f16(o[nt], aw, bb);
    }

    // ---- cross-head reduce through smem ----
    __syncthreads();   // all K/Q reads complete before overlay writes
    #pragma unroll
    for (int nt = 0; nt < 8; nt++) {
        float* p0 = fbuf + warp * 1088 + g * 68 + nt * 8 + 2 * t4;
        *(float2*)p0            = make_float2(o[nt][0], o[nt][1]);
        *(float2*)(p0 + 8 * 68) = make_float2(o[nt][2], o[nt][3]);
    }
    __syncthreads();

    {
        int i  = tid >> 4;
        int dq = (tid & 15) * 4;
        float4 acc = make_float4(0.f, 0.f, 0.f, 0.f);
        #pragma unroll
        for (int c = 0; c < 8; c++) {
            float4 v = *(const float4*)(fbuf + c * 1088 + i * 68 + dq);
            acc.x += v.x; acc.y += v.y; acc.z += v.z; acc.w += v.w;
        }
        *(float4*)(out + (size_t)b * 1024 + i * 64 + dq) = acc;
    }
}

// ---------------------------------------------------------------------------
extern "C" void kernel_launch(void* const* d_in, const int* in_sizes, int n_in,
                              void* d_out, int out_size) {
    const float* x   = (const float*)d_in[0];
    const float* fm  = (const float*)d_in[1];
    const float* Wkh = (const float*)d_in[2];
    const float* bkh = (const float*)d_in[3];
    const float* Wko = (const float*)d_in[4];
    const float* bko = (const float*)d_in[5];
    const float* Wqh = (const float*)d_in[6];
    const float* bqh = (const float*)d_in[7];
    const float* Wqo = (const float*)d_in[8];
    const float* bqo = (const float*)d_in[9];
    const float* Wvh = (const float*)d_in[10];
    const float* bvh = (const float*)d_in[11];
    const float* Wvo = (const float*)d_in[12];
    const float* bvo = (const float*)d_in[13];
    const float* pos = (const float*)d_in[14];
    float* out = (float*)d_out;

    cudaFuncSetAttribute(mlp_kernel, cudaFuncAttributeMaxDynamicSharedMemorySize,
                         SMEM_BYTES);
    cudaFuncSetAttribute(attn_kernel, cudaFuncAttributeMaxDynamicSharedMemorySize,
                         ATTN_SMEM_BYTES);

    prep_weights<<<3 * NCH, 256>>>(Wkh, Wko, Wqh, Wqo, Wvh, Wvo);

    dim3 grid(NROWS / 64, 3);
    mlp_kernel<<<grid, 512, SMEM_BYTES>>>(x, pos, bkh, bko, bqh, bqo, bvh, bvo);

    attn_kernel<<<BATCH, 256, ATTN_SMEM_BYTES>>>(fm, out);
}

// round 8
// speedup vs baseline: 2.5222x; 1.2388x over previous
#include <cuda_runtime.h>
#include <cuda_fp16.h>
#include <cstdint>
#include <math.h>

#define BATCH 2048
#define NMOL 16
#define CA 512
#define NROWS (BATCH * NMOL)   // 32768
#define NCH 37                 // 5 chunks (GEMM1, k=80) + 32 chunks (GEMM2, k=512)

// fp16 scratch for K, Q, V (96 MB) + prepped fp16 weight stages
__device__ __half g_scratch_h[3ULL * NROWS * CA];
// per (branch, chunk): 16 warp-slices x 1024 B, each slice [n_local][t4][e]
__device__ uint4 g_wstage[3 * NCH * 1024];   // 16 KB per stage

// ---------------------------------------------------------------------------
__device__ __forceinline__ uint32_t smem_u32(const void* p) {
    uint32_t a;
    asm("{ .reg .u64 t; cvta.to.shared.u64 t, %1; cvt.u32.u64 %0, t; }" : "=r"(a) : "l"(p));
    return a;
}
__device__ __forceinline__ void cpa16(uint32_t dst, const void* src) {
    asm volatile("cp.async.cg.shared.global [%0], [%1], 16;" :: "r"(dst), "l"(src));
}
#define CPA_COMMIT() asm volatile("cp.async.commit_group;" ::: "memory")

__device__ __forceinline__ void mma_f16(float d[4], const unsigned a[4], const unsigned b[2]) {
    asm volatile(
        "mma.sync.aligned.m16n8k16.row.col.f32.f16.f16.f32 "
        "{%0,%1,%2,%3}, {%4,%5,%6,%7}, {%8,%9}, {%0,%1,%2,%3};\n"
        : "+f"(d[0]), "+f"(d[1]), "+f"(d[2]), "+f"(d[3])
        : "r"(a[0]), "r"(a[1]), "r"(a[2]), "r"(a[3]),
          "r"(b[0]), "r"(b[1]));
}

__device__ __forceinline__ unsigned h2u(__half2 h) {
    return *reinterpret_cast<unsigned*>(&h);
}

// pair-interleave within a 16-group: k -> ((k&6)<<1) + ((k>>3)<<1) + (k&1)
__device__ __forceinline__ int p16(int k) {
    return ((k & 6) << 1) + (((k >> 3) & 1) << 1) + (k & 1);
}

// ---------------------------------------------------------------------------
// Prologue: weights -> fp16 per-warp slice blobs.
// halves index within a stage: (n>>5)*512 + (n&31)*16 + t4*4 + e
// where thread-quad t4 owns k in {2t4, 2t4+1, 2t4+8, 2t4+9} (e = 0..3).
// ---------------------------------------------------------------------------
__global__ void __launch_bounds__(1024)
prep_weights(const float* __restrict__ Wkh, const float* __restrict__ Wko,
             const float* __restrict__ Wqh, const float* __restrict__ Wqo,
             const float* __restrict__ Wvh, const float* __restrict__ Wvo)
{
    const int br = blockIdx.x / NCH;
    const int s  = blockIdx.x % NCH;
    const float* Wh = (br == 0) ? Wkh : (br == 1 ? Wqh : Wvh);
    const float* Wo = (br == 0) ? Wko : (br == 1 ? Wqo : Wvo);

    const float* W; int kbase, Krows;
    if (s < 5) { W = Wh; kbase = s * 16;       Krows = 70;  }
    else       { W = Wo; kbase = (s - 5) * 16; Krows = 512; }

    unsigned short* dst = (unsigned short*)&g_wstage[((size_t)br * NCH + s) * 1024];
    for (int idx = threadIdx.x; idx < 8192; idx += 1024) {
        int kl = idx >> 9;        // 0..15
        int n  = idx & 511;
        int kg = kbase + kl;
        float v = (kg < Krows) ? W[(size_t)kg * 512 + n] : 0.f;
        int t4 = (kl & 7) >> 1;
        int e  = ((kl >> 3) << 1) | (kl & 1);
        dst[(n >> 5) * 512 + (n & 31) * 16 + t4 * 4 + e] = __half_as_ushort(__float2half_rn(v));
    }
}

// ---------------------------------------------------------------------------
// Fused fp16 MLP, warp-private weight staging: zero per-chunk CTA barriers.
// smem bytes: XE [0, 10240) | H [10240, 77824) | rings [77824, 126976)
//   ring: warp w, buf b (3 deep): STAGE_OFF + w*3072 + b*1024
// ---------------------------------------------------------------------------
#define XE_OFF    0
#define H_OFF     10240
#define STAGE_OFF 77824
#define SMEM_BYTES (STAGE_OFF + 16 * 3072)   // 126976

__global__ void __launch_bounds__(512, 1)
mlp_kernel(const float* __restrict__ x, const float* __restrict__ pos,
           const float* __restrict__ bkh, const float* __restrict__ bko,
           const float* __restrict__ bqh, const float* __restrict__ bqo,
           const float* __restrict__ bvh, const float* __restrict__ bvo)
{
    extern __shared__ char smem[];
    const uint32_t smem_base = smem_u32(smem);
    const int tid  = threadIdx.x;
    const int by   = blockIdx.y;
    const int row0 = blockIdx.x * 64;

    const float* bh = (by == 0) ? bkh : (by == 1 ? bqh : bvh);
    const float* bo = (by == 0) ? bko : (by == 1 ? bqo : bvo);
    __half* outh = g_scratch_h + (size_t)by * NROWS * CA;

    const int lane = tid & 31;
    const int warp = tid >> 5;       // 16 warps, each owns 32 N cols
    const int g  = lane >> 2;
    const int t4 = lane & 3;
    const int nw = warp * 32;

    // per-warp source base: branch stages + this warp's 1KB slice + lane offset
    const char* wsrc_base = (const char*)(g_wstage + (size_t)by * NCH * 1024)
                            + warp * 1024 + lane * 16;
    const uint32_t ring = smem_base + STAGE_OFF + warp * 3072;

    auto issue_load = [&](int s) {
        const char* src = wsrc_base + (size_t)s * 16384;
        uint32_t d = ring + (s % 3) * 1024 + lane * 16;
        cpa16(d, src);
        cpa16(d + 512, src + 512);
        CPA_COMMIT();
    };

    issue_load(0);
    issue_load(1);

    // ---- build XE (fp16, pair-interleaved k order) ----
    {
        __half* XE = (__half*)(smem + XE_OFF);
        for (int idx = tid; idx < 64 * 80; idx += 512) {
            int r = idx / 80, c = idx - r * 80;
            int rg = row0 + r;
            float v = 0.f;
            if (c < 64)      v = x[(size_t)rg * 64 + c];
            else if (c < 70) v = pos[(rg & 15) * 6 + (c - 64)];
            XE[r * 80 + (c >> 4) * 16 + p16(c & 15)] = __float2half_rn(v);
        }
    }

    float acc[4][4][4];
    #pragma unroll
    for (int i = 0; i < 4; i++)
        #pragma unroll
        for (int j = 0; j < 4; j++)
            #pragma unroll
            for (int q = 0; q < 4; q++) acc[i][j][q] = 0.f;

    __syncthreads();   // XE visible to all warps

    for (int s = 0; s < NCH; ++s) {
        if (s == 5) {
            // ---- epilogue1: H = silu(D1 + bh), fp16 pair-interleaved ----
            __half* H = (__half*)(smem + H_OFF);
            #pragma unroll
            for (int mt = 0; mt < 4; mt++) {
                #pragma unroll
                for (int nt = 0; nt < 4; nt++) {
                    int col = nw + nt * 8 + 2 * t4;
                    int r0  = mt * 16 + g;
                    float b0 = bh[col], b1 = bh[col + 1];
                    int cl = col & 15;
                    int pp = ((cl & 6) << 1) + ((cl >> 3) << 1);
                    int off = r0 * 528 + (col >> 4) * 16 + pp;
                    float h0 = acc[mt][nt][0] + b0; h0 = h0 / (1.f + __expf(-h0));
                    float h1 = acc[mt][nt][1] + b1; h1 = h1 / (1.f + __expf(-h1));
                    float h2 = acc[mt][nt][2] + b0; h2 = h2 / (1.f + __expf(-h2));
                    float h3 = acc[mt][nt][3] + b1; h3 = h3 / (1.f + __expf(-h3));
                    *(__half2*)(H + off)            = __floats2half2_rn(h0, h1);
                    *(__half2*)(H + off + 8 * 528)  = __floats2half2_rn(h2, h3);
                    acc[mt][nt][0] = 0.f; acc[mt][nt][1] = 0.f;
                    acc[mt][nt][2] = 0.f; acc[mt][nt][3] = 0.f;
                }
            }
            __syncthreads();   // H visible to all warps
        }

        // per-warp wait: buffer s ready (<=1 group outstanding)
        if (s < NCH - 1) asm volatile("cp.async.wait_group 1;" ::: "memory");
        else             asm volatile("cp.async.wait_group 0;" ::: "memory");

        if (s + 2 < NCH) issue_load(s + 2);   // reuses buffer (s-1)%3: warp-local, done

        const __half* Abase; int SA, coff;
        if (s < 5) { Abase = (const __half*)(smem + XE_OFF); SA = 80;  coff = s * 16; }
        else       { Abase = (const __half*)(smem + H_OFF);  SA = 528; coff = (s - 5) * 16; }
        const __half* Bw = (const __half*)(smem + STAGE_OFF) + warp * 1536 + (s % 3) * 512;

        unsigned af[4][4], bf[4][2];
        #pragma unroll
        for (int mt = 0; mt < 4; mt++) {
            const __half* p0 = Abase + (mt * 16 + g) * SA + coff + t4 * 4;
            uint2 lo = *(const uint2*)p0;
            uint2 hi = *(const uint2*)(p0 + 8 * SA);
            af[mt][0] = lo.x; af[mt][2] = lo.y;
            af[mt][1] = hi.x; af[mt][3] = hi.y;
        }
        #pragma unroll
        for (int nt = 0; nt < 4; nt++) {
            uint2 b = *(const uint2*)(Bw + (nt * 8 + g) * 16 + t4 * 4);
            bf[nt][0] = b.x; bf[nt][1] = b.y;
        }
        #pragma unroll
        for (int mt = 0; mt < 4; mt++)
            #pragma unroll
            for (int nt = 0; nt < 4; nt++)
                mma_f16(acc[mt][nt], af[mt], bf[nt]);
    }

    // ---- epilogue2: scratch(fp16) = D2 + bo ----
    #pragma unroll
    for (int mt = 0; mt < 4; mt++) {
        #pragma unroll
        for (int nt = 0; nt < 4; nt++) {
            int col = nw + nt * 8 + 2 * t4;
            int r0  = mt * 16 + g;
            float b0 = bo[col], b1 = bo[col + 1];
            *(__half2*)(outh + (size_t)(row0 + r0) * 512 + col)
                = __floats2half2_rn(acc[mt][nt][0] + b0, acc[mt][nt][1] + b1);
            *(__half2*)(outh + (size_t)(row0 + r0 + 8) * 512 + col)
                = __floats2half2_rn(acc[mt][nt][2] + b0, acc[mt][nt][3] + b1);
        }
    }
}

// ---------------------------------------------------------------------------
// Attention, fp16 mma (unchanged from R7, ~30 us)
// ---------------------------------------------------------------------------
#define KS_OFF 0
#define QS_OFF 9216
#define VT_OFF 18432
#define ATTN_SMEM_BYTES ((VT_OFF + 12288) * 2)   // 61440

__global__ void __launch_bounds__(256)
attn_kernel(const float* __restrict__ fm, float* __restrict__ out)
{
    extern __shared__ char smem[];
    __half* smh = (__half*)smem;
    float*  fbuf = (float*)smem;

    const int b    = blockIdx.x;
    const int tid  = threadIdx.x;
    const int warp = tid >> 5;       // head c
    const int lane = tid & 31;
    const int g    = lane >> 2;
    const int t4   = lane & 3;

    const unsigned* kg32 = (const unsigned*)g_scratch_h + (size_t)b * 4096;
    const unsigned* qg32 = kg32 + 8388608;    // NROWS*CA/2
    const unsigned* vg32 = kg32 + 16777216;

    #pragma unroll
    for (int it = 0; it < 16; it++) {
        int f = tid + it * 256;
        int i = f >> 8, rem = f & 255;
        int c = rem >> 5, m = rem & 31;
        int a = 2 * m;
        int koff = (a >> 4) * 16 + p16(a & 15);
        *(unsigned*)(smh + KS_OFF + c * 1152 + i * 72 + koff) = kg32[f];
        *(unsigned*)(smh + QS_OFF + c * 1152 + i * 72 + koff) = qg32[f];
        unsigned v = vg32[f];
        int pj = p16(i);
        smh[VT_OFF + c * 1536 + a * 24 + pj]       = __ushort_as_half((unsigned short)(v & 0xFFFF));
        smh[VT_OFF + c * 1536 + (a + 1) * 24 + pj] = __ushort_as_half((unsigned short)(v >> 16));
    }
    __syncthreads();

    float d0[4] = {0.f, 0.f, 0.f, 0.f};
    float d1[4] = {0.f, 0.f, 0.f, 0.f};
    const __half* Kc = smh + KS_OFF + warp * 1152;
    const __half* Qc = smh + QS_OFF + warp * 1152;
    #pragma unroll
    for (int kc = 0; kc < 4; kc++) {
        unsigned af[4];
        uint2 lo = *(const uint2*)(Kc + g * 72 + kc * 16 + t4 * 4);
        uint2 hi = *(const uint2*)(Kc + (g + 8) * 72 + kc * 16 + t4 * 4);
        af[0] = lo.x; af[1] = hi.x; af[2] = lo.y; af[3] = hi.y;
        uint2 q0 = *(const uint2*)(Qc + g * 72 + kc * 16 + t4 * 4);
        uint2 q1 = *(const uint2*)(Qc + (g + 8) * 72 + kc * 16 + t4 * 4);
        unsigned b0[2] = {q0.x, q0.y};
        unsigned b1[2] = {q1.x, q1.y};
        mma_f16(d0, af, b0);
        mma_f16(d1, af, b1);
    }

    const float fr0 = __ldg(&fm[g]);
    const float fr1 = __ldg(&fm[g + 8]);
    float w0[4], w1[4];
    #pragma unroll
    for (int e = 0; e < 4; e++) {
        int row = (e >= 2) ? (g + 8) : g;
        float frow = (e >= 2) ? fr1 : fr0;
        int j0 = 2 * t4 + (e & 1);
        int j1 = j0 + 8;
        float fj0 = __ldg(&fm[j0]);
        float fj1 = __ldg(&fm[j1]);
        float a0 = d0[e] * 0.125f * frow * fj0;
        float a1 = d1[e] * 0.125f * frow * fj1;
        float s0 = (a0 > 20.f) ? a0 : log1pf(__expf(a0));
        float s1 = (a1 > 20.f) ? a1 : log1pf(__expf(a1));
        w0[e] = (row == j0) ? 0.f : (s0 + 1e-5f);
        w1[e] = (row == j1) ? 0.f : (s1 + 1e-5f);
    }
    float s0 = w0[0] + w0[1] + w1[0] + w1[1];
    float s1 = w0[2] + w0[3] + w1[2] + w1[3];
    s0 += __shfl_xor_sync(0xffffffffu, s0, 1);
    s0 += __shfl_xor_sync(0xffffffffu, s0, 2);
    s1 += __shfl_xor_sync(0xffffffffu, s1, 1);
    s1 += __shfl_xor_sync(0xffffffffu, s1, 2);
    float i0 = 1.f / s0, i1 = 1.f / s1;
    #pragma unroll
    for (int e = 0; e < 4; e++) {
        int j0 = 2 * t4 + (e & 1);
        float inv = (e >= 2) ? i1 : i0;
        w0[e] = w0[e] * inv * __ldg(&fm[j0]);
        w1[e] = w1[e] * inv * __ldg(&fm[j0 + 8]);
    }

    unsigned aw[4];
    aw[0] = h2u(__floats2half2_rn(w0[0], w0[1]));
    aw[1] = h2u(__floats2half2_rn(w0[2], w0[3]));
    aw[2] = h2u(__floats2half2_rn(w1[0], w1[1]));
    aw[3] = h2u(__floats2half2_rn(w1[2], w1[3]));

    float o[8][4];
    const __half* Vc = smh + VT_OFF + warp * 1536;
    #pragma unroll
    for (int nt = 0; nt < 8; nt++) {
        o[nt][0] = o[nt][1] = o[nt][2] = o[nt][3] = 0.f;
        uint2 vb = *(const uint2*)(Vc + (nt * 8 + g) * 24 + t4 * 4);
        unsigned bb[2] = {vb.x, vb.y};
        mma_f16(o[nt], aw, bb);
    }

    __syncthreads();
    #pragma unroll
    for (int nt = 0; nt < 8; nt++) {
        float* p0 = fbuf + warp * 1088 + g * 68 + nt * 8 + 2 * t4;
        *(float2*)p0            = make_float2(o[nt][0], o[nt][1]);
        *(float2*)(p0 + 8 * 68) = make_float2(o[nt][2], o[nt][3]);
    }
    __syncthreads();

    {
        int i  = tid >> 4;
        int dq = (tid & 15) * 4;
        float4 acc = make_float4(0.f, 0.f, 0.f, 0.f);
        #pragma unroll
        for (int c = 0; c < 8; c++) {
            float4 v = *(const float4*)(fbuf + c * 1088 + i * 68 + dq);
            acc.x += v.x; acc.y += v.y; acc.z += v.z; acc.w += v.w;
        }
        *(float4*)(out + (size_t)b * 1024 + i * 64 + dq) = acc;
    }
}

// ---------------------------------------------------------------------------
extern "C" void kernel_launch(void* const* d_in, const int* in_sizes, int n_in,
                              void* d_out, int out_size) {
    const float* x   = (const float*)d_in[0];
    const float* fm  = (const float*)d_in[1];
    const float* Wkh = (const float*)d_in[2];
    const float* bkh = (const float*)d_in[3];
    const float* Wko = (const float*)d_in[4];
    const float* bko = (const float*)d_in[5];
    const float* Wqh = (const float*)d_in[6];
    const float* bqh = (const float*)d_in[7];
    const float* Wqo = (const float*)d_in[8];
    const float* bqo = (const float*)d_in[9];
    const float* Wvh = (const float*)d_in[10];
    const float* bvh = (const float*)d_in[11];
    const float* Wvo = (const float*)d_in[12];
    const float* bvo = (const float*)d_in[13];
    const float* pos = (const float*)d_in[14];
    float* out = (float*)d_out;

    cudaFuncSetAttribute(mlp_kernel, cudaFuncAttributeMaxDynamicSharedMemorySize,
                         SMEM_BYTES);
    cudaFuncSetAttribute(attn_kernel, cudaFuncAttributeMaxDynamicSharedMemorySize,
                         ATTN_SMEM_BYTES);

    prep_weights<<<3 * NCH, 1024>>>(Wkh, Wko, Wqh, Wqo, Wvh, Wvo);

    dim3 grid(NROWS / 64, 3);
    mlp_kernel<<<grid, 512, SMEM_BYTES>>>(x, pos, bkh, bko, bqh, bqo, bvh, bvo);

    attn_kernel<<<BATCH, 256, ATTN_SMEM_BYTES>>>(fm, out);
}